// round 1
// baseline (speedup 1.0000x reference)
#include <cuda_runtime.h>

#define H_IN 160
#define W_IN 288
#define HO   80
#define WO   144
#define NPIX (HO*WO)          // 11520
#define BATCH 4
#define EPSV 1e-5f
#define DISP 24

// ------------------- scratch (static device memory, no allocs) ---------------
__device__ float g_y1g[BATCH*192*NPIX];   // gwc conv1+bn+lrelu out
__device__ float g_y1c[BATCH*24*NPIX];    // cat conv1+bn+lrelu out
__device__ float g_mg [BATCH*144*NPIX];   // gwc softmax mask
__device__ float g_mc [BATCH*108*NPIX];   // cat softmax mask
__device__ float g_g8 [BATCH*96*NPIX];    // gwc downsampled features
__device__ float g_c8 [BATCH*12*NPIX];    // cat downsampled features

// ------------------- conv 3x3 stride2 pad1 + BN + leaky ----------------------
// 16x16 output tile per block, 64 threads, each thread 2x2 px, OC_PB ocs.
template<int CIN, int CMID, int OC_PB>
__global__ __launch_bounds__(64) void conv1_bn_lrelu(
    const float* __restrict__ x, const float* __restrict__ w,
    const float* __restrict__ bng, const float* __restrict__ bnb,
    const float* __restrict__ bnm, const float* __restrict__ bnv,
    float* __restrict__ y)
{
    __shared__ float s_in[33*33];
    __shared__ float s_w[OC_PB*9];
    const int NOCG = CMID / OC_PB;
    int bz  = blockIdx.z;
    int b   = bz / NOCG, ocg = bz % NOCG;
    int oc0 = ocg * OC_PB;
    int ho0 = blockIdx.y * 16, wo0 = blockIdx.x * 16;
    int ih0 = 2*ho0 - 1, iw0 = 2*wo0 - 1;
    int tid = threadIdx.x;
    int ty  = tid >> 3, tx = tid & 7;

    // precompute smem-fill geometry (fixed over ic loop)
    int  goff[18]; bool gok[18]; bool wok[18];
    #pragma unroll
    for (int it = 0; it < 18; ++it) {
        int idx = tid + it*64;
        int r = idx / 33, c = idx - r*33;
        int ih = ih0 + r, iw = iw0 + c;
        wok[it] = idx < 1089;
        gok[it] = wok[it] && ih >= 0 && ih < H_IN && iw >= 0 && iw < W_IN;
        goff[it] = ih * W_IN + iw;
    }

    float acc[OC_PB][2][2];
    #pragma unroll
    for (int o = 0; o < OC_PB; ++o)
        #pragma unroll
        for (int a = 0; a < 2; ++a)
            #pragma unroll
            for (int d = 0; d < 2; ++d) acc[o][a][d] = 0.f;

    const float* xb = x + (long)b * CIN * H_IN * W_IN;
    for (int ic = 0; ic < CIN; ++ic) {
        const float* xc = xb + (long)ic * H_IN * W_IN;
        #pragma unroll
        for (int it = 0; it < 18; ++it) {
            int idx = tid + it*64;
            if (wok[it]) s_in[idx] = gok[it] ? __ldg(xc + goff[it]) : 0.f;
        }
        for (int i = tid; i < OC_PB*9; i += 64) {
            int oc = i / 9, j = i - oc*9;
            s_w[i] = w[((oc0 + oc)*CIN + ic)*9 + j];
        }
        __syncthreads();

        float v[5][5];
        #pragma unroll
        for (int r = 0; r < 5; ++r)
            #pragma unroll
            for (int c = 0; c < 5; ++c)
                v[r][c] = s_in[(4*ty + r)*33 + 4*tx + c];

        #pragma unroll
        for (int o = 0; o < OC_PB; ++o) {
            #pragma unroll
            for (int ki = 0; ki < 3; ++ki)
                #pragma unroll
                for (int kj = 0; kj < 3; ++kj) {
                    float wv = s_w[o*9 + ki*3 + kj];
                    acc[o][0][0] += wv * v[ki  ][kj  ];
                    acc[o][0][1] += wv * v[ki  ][kj+2];
                    acc[o][1][0] += wv * v[ki+2][kj  ];
                    acc[o][1][1] += wv * v[ki+2][kj+2];
                }
        }
        __syncthreads();
    }

    #pragma unroll
    for (int o = 0; o < OC_PB; ++o) {
        int oc = oc0 + o;
        float s    = bng[oc] * rsqrtf(bnv[oc] + EPSV);
        float bias = bnb[oc] - bnm[oc] * s;
        #pragma unroll
        for (int dy = 0; dy < 2; ++dy)
            #pragma unroll
            for (int dx = 0; dx < 2; ++dx) {
                int ho = ho0 + 2*ty + dy, wo = wo0 + 2*tx + dx;
                float vv = acc[o][dy][dx] * s + bias;
                vv = vv >= 0.f ? vv : 0.1f * vv;
                y[(long)(b*CMID + oc)*NPIX + ho*WO + wo] = vv;
            }
    }
}

// ------------------- 1x1 conv + softmax over 9 (per group) -------------------
// Block: 32 pixels, G*8 threads. Thread: one group (9 ocs) x 4 pixels.
template<int CMID, int G, int CK>
__global__ __launch_bounds__(G*8) void mask_softmax(
    const float* __restrict__ y1, const float* __restrict__ w2,
    float* __restrict__ mask)
{
    const int NT = G*8;
    __shared__ float s_y[CMID*32];
    __shared__ float s_w[G*9*(CK+1)];
    int b  = blockIdx.y;
    int p0 = blockIdx.x * 32;
    int tid = threadIdx.x;
    int g = tid >> 3, q = tid & 7;

    for (int i = tid; i < CMID*32; i += NT) {
        int k = i >> 5, p = i & 31;
        s_y[i] = y1[(long)(b*CMID + k)*NPIX + p0 + p];
    }

    float acc[9][4];
    #pragma unroll
    for (int j = 0; j < 9; ++j)
        #pragma unroll
        for (int i = 0; i < 4; ++i) acc[j][i] = 0.f;

    for (int c0 = 0; c0 < CMID; c0 += CK) {
        __syncthreads();
        for (int i = tid; i < G*9*CK; i += NT) {
            int oc = i / CK, kk = i - oc*CK;
            s_w[oc*(CK+1) + kk] = w2[oc*CMID + c0 + kk];
        }
        __syncthreads();
        #pragma unroll 4
        for (int kk = 0; kk < CK; ++kk) {
            float yv[4];
            #pragma unroll
            for (int i = 0; i < 4; ++i) yv[i] = s_y[(c0 + kk)*32 + q + 8*i];
            #pragma unroll
            for (int j = 0; j < 9; ++j) {
                float wv = s_w[(g*9 + j)*(CK+1) + kk];
                #pragma unroll
                for (int i = 0; i < 4; ++i) acc[j][i] += wv * yv[i];
            }
        }
    }

    #pragma unroll
    for (int i = 0; i < 4; ++i) {
        float m = acc[0][i];
        #pragma unroll
        for (int j = 1; j < 9; ++j) m = fmaxf(m, acc[j][i]);
        float e[9], sum = 0.f;
        #pragma unroll
        for (int j = 0; j < 9; ++j) { e[j] = __expf(acc[j][i] - m); sum += e[j]; }
        float rs = 1.f / sum;
        #pragma unroll
        for (int j = 0; j < 9; ++j)
            mask[(long)(b*G*9 + g*9 + j)*NPIX + p0 + q + 8*i] = e[j] * rs;
    }
}

// ------------------- unfold-weighted-sum aggregation -------------------------
// NOTE: downsample group = c % GROUPS (from reshape(b, c//groups, groups, ...)).
template<int C, int GROUPS>
__global__ __launch_bounds__(256) void aggregate(
    const float* __restrict__ x, const float* __restrict__ mask,
    float* __restrict__ out)
{
    int idx = blockIdx.x * blockDim.x + threadIdx.x;
    if (idx >= BATCH*C*NPIX) return;
    int wo = idx % WO;
    int t  = idx / WO;
    int ho = t % HO; t /= HO;
    int c  = t % C;
    int b  = t / C;
    int g  = c % GROUPS;

    const float* xb = x + (long)(b*C + c) * H_IN * W_IN;
    const float* mb = mask + (long)(b*GROUPS*9 + g*9) * NPIX + ho*WO + wo;

    float acc = 0.f;
    #pragma unroll
    for (int ki = 0; ki < 3; ++ki) {
        int ih = 2*ho - 1 + ki;
        bool okh = (ih >= 0) && (ih < H_IN);
        #pragma unroll
        for (int kj = 0; kj < 3; ++kj) {
            int iw = 2*wo - 1 + kj;
            float xv = (okh && iw >= 0 && iw < W_IN) ? __ldg(xb + ih*W_IN + iw) : 0.f;
            acc += __ldg(mb + (ki*3 + kj)*NPIX) * xv;
        }
    }
    out[idx] = acc;
}

// ------------------- group-wise correlation volume ---------------------------
// out[b2, g(0..7), d, h, w] = mean_c l[b2, g*12+c, h, w] * r[b2, g*12+c, h, w-d]
__global__ __launch_bounds__(128) void vol_gwc(const float* __restrict__ g8,
                                               float* __restrict__ out)
{
    int idx = blockIdx.x * blockDim.x + threadIdx.x;   // 2*8*NPIX
    int w  = idx % WO;
    int t  = idx / WO;
    int h  = t % HO; t /= HO;
    int g  = t % 8;
    int b2 = t / 8;

    const float* lp = g8 + (long)(b2*96 + g*12) * NPIX + h*WO + w;
    const float* rp = g8 + (long)((b2+2)*96 + g*12) * NPIX + h*WO;
    float lv[12];
    #pragma unroll
    for (int c = 0; c < 12; ++c) lv[c] = lp[c*NPIX];

    float* ob = out + (long)(b2*32 + g) * DISP * NPIX + h*WO + w;
    for (int d = 0; d < DISP; ++d) {
        float val = 0.f;
        if (d <= w) {
            float s = 0.f;
            #pragma unroll
            for (int c = 0; c < 12; ++c) s += lv[c] * __ldg(rp + c*NPIX + (w - d));
            val = s * (1.f/12.f);
        }
        ob[(long)d*NPIX] = val;
    }
}

// ------------------- concat volume -------------------------------------------
__global__ __launch_bounds__(256) void vol_cat(const float* __restrict__ c8,
                                               float* __restrict__ out)
{
    int idx = blockIdx.x * blockDim.x + threadIdx.x;   // 2*24*24*NPIX
    int w  = idx % WO;
    int t  = idx / WO;
    int h  = t % HO; t /= HO;
    int d  = t % DISP; t /= DISP;
    int ch = t % 24;
    int b2 = t / 24;

    float val = 0.f;
    if (w >= d) {
        if (ch < 12)
            val = __ldg(c8 + (long)(b2*12 + ch) * NPIX + h*WO + w);
        else
            val = __ldg(c8 + (long)((b2+2)*12 + (ch-12)) * NPIX + h*WO + (w - d));
    }
    out[(long)(b2*32 + 8 + ch) * DISP * NPIX + (long)d*NPIX + h*WO + w] = val;
}

// ------------------- launch --------------------------------------------------
extern "C" void kernel_launch(void* const* d_in, const int* in_sizes, int n_in,
                              void* d_out, int out_size)
{
    const float* gwc_f = (const float*)d_in[0];
    const float* cat_f = (const float*)d_in[1];
    const float* g_w1  = (const float*)d_in[2];
    const float* g_bg  = (const float*)d_in[3];
    const float* g_bb  = (const float*)d_in[4];
    const float* g_bm  = (const float*)d_in[5];
    const float* g_bv  = (const float*)d_in[6];
    const float* g_w2  = (const float*)d_in[7];
    const float* c_w1  = (const float*)d_in[8];
    const float* c_bg  = (const float*)d_in[9];
    const float* c_bb  = (const float*)d_in[10];
    const float* c_bm  = (const float*)d_in[11];
    const float* c_bv  = (const float*)d_in[12];
    const float* c_w2  = (const float*)d_in[13];
    float* out = (float*)d_out;

    float *y1g, *y1c, *mg, *mc, *g8, *c8;
    cudaGetSymbolAddress((void**)&y1g, g_y1g);
    cudaGetSymbolAddress((void**)&y1c, g_y1c);
    cudaGetSymbolAddress((void**)&mg,  g_mg);
    cudaGetSymbolAddress((void**)&mc,  g_mc);
    cudaGetSymbolAddress((void**)&g8,  g_g8);
    cudaGetSymbolAddress((void**)&c8,  g_c8);

    // 1) conv1 + BN + leaky
    conv1_bn_lrelu<96,192,16><<<dim3(9,5,BATCH*12), 64>>>(gwc_f, g_w1, g_bg, g_bb, g_bm, g_bv, y1g);
    conv1_bn_lrelu<12, 24, 8><<<dim3(9,5,BATCH* 3), 64>>>(cat_f, c_w1, c_bg, c_bb, c_bm, c_bv, y1c);

    // 2) 1x1 conv + softmax masks
    mask_softmax<192,16,32><<<dim3(360,BATCH), 128>>>(y1g, g_w2, mg);
    mask_softmax< 24,12,24><<<dim3(360,BATCH),  96>>>(y1c, c_w2, mc);

    // 3) adaptive aggregation
    aggregate<96,16><<<(BATCH*96*NPIX)/256, 256>>>(gwc_f, mg, g8);
    aggregate<12,12><<<(BATCH*12*NPIX)/256, 256>>>(cat_f, mc, c8);

    // 4) cost volumes into output
    vol_gwc<<<(2*8*NPIX)/128, 128>>>(g8, out);
    vol_cat<<<(2*24*DISP*NPIX)/256, 256>>>(c8, out);
}

// round 3
// speedup vs baseline: 1.8449x; 1.8449x over previous
#include <cuda_runtime.h>
#include <cstdint>

#define H_IN 160
#define W_IN 288
#define HO   80
#define WO   144
#define NPIX (HO*WO)          // 11520
#define BATCH 4
#define EPSV 1e-5f
#define DISP 24

// ------------------- scratch (static device memory, no allocs) ---------------
__device__ float g_y1g[BATCH*192*NPIX];   // gwc conv1+bn+lrelu out
__device__ float g_y1c[BATCH*24*NPIX];    // cat conv1+bn+lrelu out
__device__ float g_mg [BATCH*144*NPIX];   // gwc softmax mask
__device__ float g_mc [BATCH*108*NPIX];   // cat softmax mask
__device__ float g_g8 [BATCH*96*NPIX];    // gwc downsampled features
__device__ float g_c8 [BATCH*12*NPIX];    // cat downsampled features
__device__ float g_wr [192*864];          // reordered gwc conv1 weights [oc][tap][ic]

// ===================== small helpers ========================================
__device__ __forceinline__ unsigned smem_u32(const void* p){
    unsigned a;
    asm("{ .reg .u64 t; cvta.to.shared.u64 t, %1; cvt.u32.u64 %0, t; }"
        : "=r"(a) : "l"(p));
    return a;
}
__device__ __forceinline__ unsigned short bf16hi(float x){
    unsigned u = __float_as_uint(x);
    unsigned r = u + 0x7fffu + ((u >> 16) & 1u);
    return (unsigned short)(r >> 16);
}
__device__ __forceinline__ float bf16f(unsigned short h){
    return __uint_as_float(((unsigned)h) << 16);
}
__device__ __forceinline__ unsigned pack2(unsigned short a, unsigned short b){
    return (unsigned)a | ((unsigned)b << 16);
}
__device__ __forceinline__ void ldm4(unsigned* r, unsigned addr){
    asm volatile("ldmatrix.sync.aligned.m8n8.x4.shared.b16 {%0,%1,%2,%3}, [%4];"
        : "=r"(r[0]), "=r"(r[1]), "=r"(r[2]), "=r"(r[3]) : "r"(addr));
}
__device__ __forceinline__ void mma_bf16(float* c, const unsigned* a,
                                         unsigned b0, unsigned b1){
    asm volatile("mma.sync.aligned.m16n8k16.row.col.f32.bf16.bf16.f32 "
        "{%0,%1,%2,%3}, {%4,%5,%6,%7}, {%8,%9}, {%0,%1,%2,%3};"
        : "+f"(c[0]), "+f"(c[1]), "+f"(c[2]), "+f"(c[3])
        : "r"(a[0]), "r"(a[1]), "r"(a[2]), "r"(a[3]), "r"(b0), "r"(b1));
}

// ===================== weight reorder: [oc][ic][tap] -> [oc][tap][ic] ========
__global__ __launch_bounds__(256) void wreorder(const float* __restrict__ w,
                                                float* __restrict__ wr)
{
    int idx = blockIdx.x * 256 + threadIdx.x;   // 192*864
    int oc = idx / 864;
    int r  = idx - oc*864;
    int tap = r / 96, ic = r - tap*96;
    wr[idx] = w[oc*864 + ic*9 + tap];
}

// ===================== conv1 gwc: implicit GEMM on mma.sync bf16 =============
// CTA tile: M=64 pixels x N=192 oc. K=864 (k = tap*96+ic), 27 chunks of 32.
// 3-pass bf16 split (hi/lo) for fp32-grade accuracy.
#define A_HI 1536
#define A_LO (A_HI + 5120)
#define B_HI (A_LO + 5120)
#define B_LO (B_HI + 15360)
#define SMEM_CONV1 (1536 + 64*193*4)   // 50944: BN table + epi buffer (reuses A/B)

__global__ __launch_bounds__(256, 1) void conv1_gwc_mma(
    const float* __restrict__ x, const float* __restrict__ wr,
    const float* __restrict__ bng, const float* __restrict__ bnb,
    const float* __restrict__ bnm, const float* __restrict__ bnv,
    float* __restrict__ y)
{
    extern __shared__ char smem[];
    const unsigned sb = smem_u32(smem);
    const int tid = threadIdx.x;
    const int wid = tid >> 5, lane = tid & 31;
    float* sbn = (float*)smem;

    if (tid < 192) {
        float s = bng[tid] * rsqrtf(bnv[tid] + EPSV);
        sbn[tid] = s;
        sbn[192 + tid] = bnb[tid] - bnm[tid] * s;
    }

    // ---- gather geometry ----
    const int wm = wid & 1, wn = wid >> 1;          // warp tile: rows wm*32, cols wn*48
    const int m  = wm*32 + lane;                    // A-gather pixel row (0..63)
    const int p  = blockIdx.x*64 + m;
    const int b  = p / NPIX;
    const int r  = p - b*NPIX;
    const int ho = r / WO, wo = r - (r/WO)*WO;
    const float* xb = x + (size_t)b * 96 * H_IN * W_IN;
    const int kkb = (wid >> 1) * 8;                 // A-gather ic offset (0..24)

    const int brow = wid*2 + (lane >> 4);           // B-gather base row
    const int kk2  = lane & 15;                     // B-gather kk pair

    unsigned* sAhi = (unsigned*)(smem + A_HI);
    unsigned* sAlo = (unsigned*)(smem + A_LO);
    unsigned* sBhi = (unsigned*)(smem + B_HI);
    unsigned* sBlo = (unsigned*)(smem + B_LO);

    // ldmatrix base addresses (lane part precomputed)
    const unsigned aHiB = sb + A_HI + ((wm*32 + (lane&15))*40 + (lane>>4)*8)*2;
    const unsigned aLoB = aHiB + (A_LO - A_HI);
    const unsigned bHiB = sb + B_HI + ((wn*48 + (lane&15))*40 + (lane>>4)*8)*2;
    const unsigned bLoB = bHiB + (B_LO - B_HI);

    float acc[2][6][4];
    #pragma unroll
    for (int f = 0; f < 2; ++f)
        #pragma unroll
        for (int g = 0; g < 6; ++g)
            #pragma unroll
            for (int i = 0; i < 4; ++i) acc[f][g][i] = 0.f;

    float  av[8];
    float2 bv[12];

    // gather chunk 0
    {
        const int c = 0;
        int tap = 0, ic0 = kkb;
        int ih = 2*ho - 1, iw = 2*wo - 1;
        bool ok = (ih >= 0) && (iw >= 0);
        const float* ptr = xb + ((size_t)ic0*H_IN + ih)*W_IN + iw;
        #pragma unroll
        for (int j = 0; j < 8; ++j)
            av[j] = ok ? __ldg(ptr + (size_t)j*H_IN*W_IN) : 0.f;
        #pragma unroll
        for (int i = 0; i < 12; ++i)
            bv[i] = __ldg((const float2*)(wr + (size_t)(brow + i*16)*864 + c*32 + kk2*2));
        (void)tap;
    }

    for (int c = 0; c < 27; ++c) {
        // convert + STS current chunk
        {
            int wbase = m*20 + (kkb >> 1);
            #pragma unroll
            for (int jj = 0; jj < 4; ++jj) {
                float v0 = av[2*jj], v1 = av[2*jj+1];
                unsigned short h0 = bf16hi(v0), h1 = bf16hi(v1);
                unsigned short l0 = bf16hi(v0 - bf16f(h0));
                unsigned short l1 = bf16hi(v1 - bf16f(h1));
                sAhi[wbase + jj] = pack2(h0, h1);
                sAlo[wbase + jj] = pack2(l0, l1);
            }
            #pragma unroll
            for (int i = 0; i < 12; ++i) {
                int row = brow + i*16;
                float v0 = bv[i].x, v1 = bv[i].y;
                unsigned short h0 = bf16hi(v0), h1 = bf16hi(v1);
                unsigned short l0 = bf16hi(v0 - bf16f(h0));
                unsigned short l1 = bf16hi(v1 - bf16f(h1));
                sBhi[row*20 + kk2] = pack2(h0, h1);
                sBlo[row*20 + kk2] = pack2(l0, l1);
            }
        }
        __syncthreads();

        // prefetch next chunk
        if (c < 26) {
            int cn = c + 1;
            int tap = cn / 3;
            int ic0 = (cn - tap*3)*32 + kkb;
            int ki = tap / 3, kj = tap - ki*3;
            int ih = 2*ho - 1 + ki, iw = 2*wo - 1 + kj;
            bool ok = (ih >= 0) && (iw >= 0);
            const float* ptr = xb + ((size_t)ic0*H_IN + ih)*W_IN + iw;
            #pragma unroll
            for (int j = 0; j < 8; ++j)
                av[j] = ok ? __ldg(ptr + (size_t)j*H_IN*W_IN) : 0.f;
            #pragma unroll
            for (int i = 0; i < 12; ++i)
                bv[i] = __ldg((const float2*)(wr + (size_t)(brow + i*16)*864 + cn*32 + kk2*2));
        }

        // MMA on current smem chunk
        #pragma unroll
        for (int kst = 0; kst < 2; ++kst) {
            unsigned ko = kst*32;
            unsigned ah[2][4], al[2][4];
            ldm4(ah[0], aHiB + ko);
            ldm4(ah[1], aHiB + 1280 + ko);
            ldm4(al[0], aLoB + ko);
            ldm4(al[1], aLoB + 1280 + ko);
            #pragma unroll
            for (int g2 = 0; g2 < 3; ++g2) {
                unsigned bh[4], bl[4];
                ldm4(bh, bHiB + g2*1280 + ko);
                ldm4(bl, bLoB + g2*1280 + ko);
                #pragma unroll
                for (int f = 0; f < 2; ++f) {
                    mma_bf16(acc[f][2*g2],   ah[f], bh[0], bh[2]);
                    mma_bf16(acc[f][2*g2+1], ah[f], bh[1], bh[3]);
                    mma_bf16(acc[f][2*g2],   ah[f], bl[0], bl[2]);
                    mma_bf16(acc[f][2*g2+1], ah[f], bl[1], bl[3]);
                    mma_bf16(acc[f][2*g2],   al[f], bh[0], bh[2]);
                    mma_bf16(acc[f][2*g2+1], al[f], bh[1], bh[3]);
                }
            }
        }
        __syncthreads();
    }

    // ---- epilogue: BN + leaky via smem transpose, coalesced store ----
    float* sEpi = (float*)(smem + 1536);
    #pragma unroll
    for (int f = 0; f < 2; ++f) {
        int row0 = wm*32 + f*16 + (lane >> 2);
        #pragma unroll
        for (int g = 0; g < 6; ++g) {
            int col0 = wn*48 + g*8 + 2*(lane & 3);
            float s0 = sbn[col0],     b0v = sbn[192 + col0];
            float s1 = sbn[col0 + 1], b1v = sbn[192 + col0 + 1];
            float v;
            v = acc[f][g][0]*s0 + b0v; v = v >= 0.f ? v : 0.1f*v; sEpi[ row0   *193 + col0  ] = v;
            v = acc[f][g][1]*s1 + b1v; v = v >= 0.f ? v : 0.1f*v; sEpi[ row0   *193 + col0+1] = v;
            v = acc[f][g][2]*s0 + b0v; v = v >= 0.f ? v : 0.1f*v; sEpi[(row0+8)*193 + col0  ] = v;
            v = acc[f][g][3]*s1 + b1v; v = v >= 0.f ? v : 0.1f*v; sEpi[(row0+8)*193 + col0+1] = v;
        }
    }
    __syncthreads();

    int p0 = blockIdx.x*64;
    int bb = p0 / NPIX;
    int rb = p0 - bb*NPIX;
    #pragma unroll 4
    for (int i = 0; i < 48; ++i) {
        int idx = tid + i*256;
        int mm = idx & 63, oc = idx >> 6;
        y[((size_t)bb*192 + oc)*NPIX + rb + mm] = sEpi[mm*193 + oc];
    }
}

// ------------------- conv 3x3 stride2 pad1 + BN + leaky (fp32, cat path) -----
template<int CIN, int CMID, int OC_PB>
__global__ __launch_bounds__(64) void conv1_bn_lrelu(
    const float* __restrict__ x, const float* __restrict__ w,
    const float* __restrict__ bng, const float* __restrict__ bnb,
    const float* __restrict__ bnm, const float* __restrict__ bnv,
    float* __restrict__ y)
{
    __shared__ float s_in[33*33];
    __shared__ float s_w[OC_PB*9];
    const int NOCG = CMID / OC_PB;
    int bz  = blockIdx.z;
    int b   = bz / NOCG, ocg = bz % NOCG;
    int oc0 = ocg * OC_PB;
    int ho0 = blockIdx.y * 16, wo0 = blockIdx.x * 16;
    int ih0 = 2*ho0 - 1, iw0 = 2*wo0 - 1;
    int tid = threadIdx.x;
    int ty  = tid >> 3, tx = tid & 7;

    int  goff[18]; bool gok[18]; bool wok[18];
    #pragma unroll
    for (int it = 0; it < 18; ++it) {
        int idx = tid + it*64;
        int r = idx / 33, c = idx - r*33;
        int ih = ih0 + r, iw = iw0 + c;
        wok[it] = idx < 1089;
        gok[it] = wok[it] && ih >= 0 && ih < H_IN && iw >= 0 && iw < W_IN;
        goff[it] = ih * W_IN + iw;
    }

    float acc[OC_PB][2][2];
    #pragma unroll
    for (int o = 0; o < OC_PB; ++o)
        #pragma unroll
        for (int a = 0; a < 2; ++a)
            #pragma unroll
            for (int d = 0; d < 2; ++d) acc[o][a][d] = 0.f;

    const float* xb = x + (long)b * CIN * H_IN * W_IN;
    for (int ic = 0; ic < CIN; ++ic) {
        const float* xc = xb + (long)ic * H_IN * W_IN;
        #pragma unroll
        for (int it = 0; it < 18; ++it) {
            int idx = tid + it*64;
            if (wok[it]) s_in[idx] = gok[it] ? __ldg(xc + goff[it]) : 0.f;
        }
        for (int i = tid; i < OC_PB*9; i += 64) {
            int oc = i / 9, j = i - oc*9;
            s_w[i] = w[((oc0 + oc)*CIN + ic)*9 + j];
        }
        __syncthreads();

        float v[5][5];
        #pragma unroll
        for (int r = 0; r < 5; ++r)
            #pragma unroll
            for (int c = 0; c < 5; ++c)
                v[r][c] = s_in[(4*ty + r)*33 + 4*tx + c];

        #pragma unroll
        for (int o = 0; o < OC_PB; ++o) {
            #pragma unroll
            for (int ki = 0; ki < 3; ++ki)
                #pragma unroll
                for (int kj = 0; kj < 3; ++kj) {
                    float wv = s_w[o*9 + ki*3 + kj];
                    acc[o][0][0] += wv * v[ki  ][kj  ];
                    acc[o][0][1] += wv * v[ki  ][kj+2];
                    acc[o][1][0] += wv * v[ki+2][kj  ];
                    acc[o][1][1] += wv * v[ki+2][kj+2];
                }
        }
        __syncthreads();
    }

    #pragma unroll
    for (int o = 0; o < OC_PB; ++o) {
        int oc = oc0 + o;
        float s    = bng[oc] * rsqrtf(bnv[oc] + EPSV);
        float bias = bnb[oc] - bnm[oc] * s;
        #pragma unroll
        for (int dy = 0; dy < 2; ++dy)
            #pragma unroll
            for (int dx = 0; dx < 2; ++dx) {
                int ho = ho0 + 2*ty + dy, wo = wo0 + 2*tx + dx;
                float vv = acc[o][dy][dx] * s + bias;
                vv = vv >= 0.f ? vv : 0.1f * vv;
                y[(long)(b*CMID + oc)*NPIX + ho*WO + wo] = vv;
            }
    }
}

// ------------------- 1x1 conv + softmax over 9 (per group) -------------------
template<int CMID, int G, int CK>
__global__ __launch_bounds__(G*8) void mask_softmax(
    const float* __restrict__ y1, const float* __restrict__ w2,
    float* __restrict__ mask)
{
    const int NT = G*8;
    __shared__ float s_y[CMID*32];
    __shared__ float s_w[G*9*(CK+1)];
    int b  = blockIdx.y;
    int p0 = blockIdx.x * 32;
    int tid = threadIdx.x;
    int g = tid >> 3, q = tid & 7;

    for (int i = tid; i < CMID*32; i += NT) {
        int k = i >> 5, p = i & 31;
        s_y[i] = y1[(long)(b*CMID + k)*NPIX + p0 + p];
    }

    float acc[9][4];
    #pragma unroll
    for (int j = 0; j < 9; ++j)
        #pragma unroll
        for (int i = 0; i < 4; ++i) acc[j][i] = 0.f;

    for (int c0 = 0; c0 < CMID; c0 += CK) {
        __syncthreads();
        for (int i = tid; i < G*9*CK; i += NT) {
            int oc = i / CK, kk = i - oc*CK;
            s_w[oc*(CK+1) + kk] = w2[oc*CMID + c0 + kk];
        }
        __syncthreads();
        #pragma unroll 4
        for (int kk = 0; kk < CK; ++kk) {
            float yv[4];
            #pragma unroll
            for (int i = 0; i < 4; ++i) yv[i] = s_y[(c0 + kk)*32 + q + 8*i];
            #pragma unroll
            for (int j = 0; j < 9; ++j) {
                float wv = s_w[(g*9 + j)*(CK+1) + kk];
                #pragma unroll
                for (int i = 0; i < 4; ++i) acc[j][i] += wv * yv[i];
            }
        }
    }

    #pragma unroll
    for (int i = 0; i < 4; ++i) {
        float m = acc[0][i];
        #pragma unroll
        for (int j = 1; j < 9; ++j) m = fmaxf(m, acc[j][i]);
        float e[9], sum = 0.f;
        #pragma unroll
        for (int j = 0; j < 9; ++j) { e[j] = __expf(acc[j][i] - m); sum += e[j]; }
        float rs = 1.f / sum;
        #pragma unroll
        for (int j = 0; j < 9; ++j)
            mask[(long)(b*G*9 + g*9 + j)*NPIX + p0 + q + 8*i] = e[j] * rs;
    }
}

// ------------------- unfold-weighted-sum aggregation -------------------------
template<int C, int GROUPS>
__global__ __launch_bounds__(256) void aggregate(
    const float* __restrict__ x, const float* __restrict__ mask,
    float* __restrict__ out)
{
    int idx = blockIdx.x * blockDim.x + threadIdx.x;
    if (idx >= BATCH*C*NPIX) return;
    int wo = idx % WO;
    int t  = idx / WO;
    int ho = t % HO; t /= HO;
    int c  = t % C;
    int b  = t / C;
    int g  = c % GROUPS;

    const float* xb = x + (long)(b*C + c) * H_IN * W_IN;
    const float* mb = mask + (long)(b*GROUPS*9 + g*9) * NPIX + ho*WO + wo;

    float acc = 0.f;
    #pragma unroll
    for (int ki = 0; ki < 3; ++ki) {
        int ih = 2*ho - 1 + ki;
        bool okh = (ih >= 0) && (ih < H_IN);
        #pragma unroll
        for (int kj = 0; kj < 3; ++kj) {
            int iw = 2*wo - 1 + kj;
            float xv = (okh && iw >= 0 && iw < W_IN) ? __ldg(xb + ih*W_IN + iw) : 0.f;
            acc += __ldg(mb + (ki*3 + kj)*NPIX) * xv;
        }
    }
    out[idx] = acc;
}

// ------------------- group-wise correlation volume ---------------------------
__global__ __launch_bounds__(128) void vol_gwc(const float* __restrict__ g8,
                                               float* __restrict__ out)
{
    int idx = blockIdx.x * blockDim.x + threadIdx.x;
    int w  = idx % WO;
    int t  = idx / WO;
    int h  = t % HO; t /= HO;
    int g  = t % 8;
    int b2 = t / 8;

    const float* lp = g8 + (long)(b2*96 + g*12) * NPIX + h*WO + w;
    const float* rp = g8 + (long)((b2+2)*96 + g*12) * NPIX + h*WO;
    float lv[12];
    #pragma unroll
    for (int c = 0; c < 12; ++c) lv[c] = lp[c*NPIX];

    float* ob = out + (long)(b2*32 + g) * DISP * NPIX + h*WO + w;
    for (int d = 0; d < DISP; ++d) {
        float val = 0.f;
        if (d <= w) {
            float s = 0.f;
            #pragma unroll
            for (int c = 0; c < 12; ++c) s += lv[c] * __ldg(rp + c*NPIX + (w - d));
            val = s * (1.f/12.f);
        }
        ob[(long)d*NPIX] = val;
    }
}

// ------------------- concat volume -------------------------------------------
__global__ __launch_bounds__(256) void vol_cat(const float* __restrict__ c8,
                                               float* __restrict__ out)
{
    int idx = blockIdx.x * blockDim.x + threadIdx.x;
    int w  = idx % WO;
    int t  = idx / WO;
    int h  = t % HO; t /= HO;
    int d  = t % DISP; t /= DISP;
    int ch = t % 24;
    int b2 = t / 24;

    float val = 0.f;
    if (w >= d) {
        if (ch < 12)
            val = __ldg(c8 + (long)(b2*12 + ch) * NPIX + h*WO + w);
        else
            val = __ldg(c8 + (long)((b2+2)*12 + (ch-12)) * NPIX + h*WO + (w - d));
    }
    out[(long)(b2*32 + 8 + ch) * DISP * NPIX + (long)d*NPIX + h*WO + w] = val;
}

// ------------------- launch --------------------------------------------------
extern "C" void kernel_launch(void* const* d_in, const int* in_sizes, int n_in,
                              void* d_out, int out_size)
{
    const float* gwc_f = (const float*)d_in[0];
    const float* cat_f = (const float*)d_in[1];
    const float* g_w1  = (const float*)d_in[2];
    const float* g_bg  = (const float*)d_in[3];
    const float* g_bb  = (const float*)d_in[4];
    const float* g_bm  = (const float*)d_in[5];
    const float* g_bv  = (const float*)d_in[6];
    const float* g_w2  = (const float*)d_in[7];
    const float* c_w1  = (const float*)d_in[8];
    const float* c_bg  = (const float*)d_in[9];
    const float* c_bb  = (const float*)d_in[10];
    const float* c_bm  = (const float*)d_in[11];
    const float* c_bv  = (const float*)d_in[12];
    const float* c_w2  = (const float*)d_in[13];
    float* out = (float*)d_out;

    float *y1g, *y1c, *mg, *mc, *g8, *c8, *wr;
    cudaGetSymbolAddress((void**)&y1g, g_y1g);
    cudaGetSymbolAddress((void**)&y1c, g_y1c);
    cudaGetSymbolAddress((void**)&mg,  g_mg);
    cudaGetSymbolAddress((void**)&mc,  g_mc);
    cudaGetSymbolAddress((void**)&g8,  g_g8);
    cudaGetSymbolAddress((void**)&c8,  g_c8);
    cudaGetSymbolAddress((void**)&wr,  g_wr);

    // 0) weight reorder for tensorized conv1
    wreorder<<<648, 256>>>(g_w1, wr);

    // 1) conv1 + BN + leaky
    cudaFuncSetAttribute(conv1_gwc_mma, cudaFuncAttributeMaxDynamicSharedMemorySize, SMEM_CONV1);
    conv1_gwc_mma<<<720, 256, SMEM_CONV1>>>(gwc_f, wr, g_bg, g_bb, g_bm, g_bv, y1g);
    conv1_bn_lrelu<12, 24, 8><<<dim3(9,5,BATCH*3), 64>>>(cat_f, c_w1, c_bg, c_bb, c_bm, c_bv, y1c);

    // 2) 1x1 conv + softmax masks
    mask_softmax<192,16,32><<<dim3(360,BATCH), 128>>>(y1g, g_w2, mg);
    mask_softmax< 24,12,24><<<dim3(360,BATCH),  96>>>(y1c, c_w2, mc);

    // 3) adaptive aggregation
    aggregate<96,16><<<(BATCH*96*NPIX)/256, 256>>>(gwc_f, mg, g8);
    aggregate<12,12><<<(BATCH*12*NPIX)/256, 256>>>(cat_f, mc, c8);

    // 4) cost volumes into output
    vol_gwc<<<(2*8*NPIX)/128, 128>>>(g8, out);
    vol_cat<<<(2*24*DISP*NPIX)/256, 256>>>(c8, out);
}

// round 4
// speedup vs baseline: 2.0603x; 1.1168x over previous
#include <cuda_runtime.h>
#include <cstdint>

#define H_IN 160
#define W_IN 288
#define HO   80
#define WO   144
#define NPIX (HO*WO)          // 11520
#define BATCH 4
#define EPSV 1e-5f
#define DISP 24

// ------------------- scratch (static device memory, no allocs) ---------------
__device__ float g_y1g[BATCH*192*NPIX];   // gwc conv1+bn+lrelu out
__device__ float g_y1c[BATCH*24*NPIX];    // cat conv1+bn+lrelu out
__device__ float g_mg [BATCH*144*NPIX];   // gwc softmax mask
__device__ float g_mc [BATCH*108*NPIX];   // cat softmax mask
__device__ float g_g8 [BATCH*96*NPIX];    // gwc downsampled features
__device__ float g_c8 [BATCH*12*NPIX];    // cat downsampled features
__device__ float g_wr [192*864];          // reordered gwc conv1 weights [oc][tap][ic]

// ===================== small helpers ========================================
__device__ __forceinline__ unsigned smem_u32(const void* p){
    unsigned a;
    asm("{ .reg .u64 t; cvta.to.shared.u64 t, %1; cvt.u32.u64 %0, t; }"
        : "=r"(a) : "l"(p));
    return a;
}
__device__ __forceinline__ unsigned short bf16hi(float x){
    unsigned u = __float_as_uint(x);
    unsigned r = u + 0x7fffu + ((u >> 16) & 1u);
    return (unsigned short)(r >> 16);
}
__device__ __forceinline__ float bf16f(unsigned short h){
    return __uint_as_float(((unsigned)h) << 16);
}
__device__ __forceinline__ unsigned pack2(unsigned short a, unsigned short b){
    return (unsigned)a | ((unsigned)b << 16);
}
__device__ __forceinline__ void ldm4(unsigned* r, unsigned addr){
    asm volatile("ldmatrix.sync.aligned.m8n8.x4.shared.b16 {%0,%1,%2,%3}, [%4];"
        : "=r"(r[0]), "=r"(r[1]), "=r"(r[2]), "=r"(r[3]) : "r"(addr));
}
__device__ __forceinline__ void mma_bf16(float* c, const unsigned* a,
                                         unsigned b0, unsigned b1){
    asm volatile("mma.sync.aligned.m16n8k16.row.col.f32.bf16.bf16.f32 "
        "{%0,%1,%2,%3}, {%4,%5,%6,%7}, {%8,%9}, {%0,%1,%2,%3};"
        : "+f"(c[0]), "+f"(c[1]), "+f"(c[2]), "+f"(c[3])
        : "r"(a[0]), "r"(a[1]), "r"(a[2]), "r"(a[3]), "r"(b0), "r"(b1));
}

// ===================== weight reorder: [oc][ic][tap] -> [oc][tap][ic] ========
__global__ __launch_bounds__(256) void wreorder(const float* __restrict__ w,
                                                float* __restrict__ wr)
{
    int idx = blockIdx.x * 256 + threadIdx.x;   // 192*864
    int oc = idx / 864;
    int r  = idx - oc*864;
    int tap = r / 96, ic = r - tap*96;
    wr[idx] = w[oc*864 + ic*9 + tap];
}

// ===================== conv1 gwc: implicit GEMM on mma.sync bf16 =============
#define A_HI 1536
#define A_LO (A_HI + 5120)
#define B_HI (A_LO + 5120)
#define B_LO (B_HI + 15360)
#define SMEM_CONV1 (1536 + 64*193*4)   // 50944

__global__ __launch_bounds__(256, 1) void conv1_gwc_mma(
    const float* __restrict__ x, const float* __restrict__ wr,
    const float* __restrict__ bng, const float* __restrict__ bnb,
    const float* __restrict__ bnm, const float* __restrict__ bnv,
    float* __restrict__ y)
{
    extern __shared__ char smem[];
    const unsigned sb = smem_u32(smem);
    const int tid = threadIdx.x;
    const int wid = tid >> 5, lane = tid & 31;
    float* sbn = (float*)smem;

    if (tid < 192) {
        float s = bng[tid] * rsqrtf(bnv[tid] + EPSV);
        sbn[tid] = s;
        sbn[192 + tid] = bnb[tid] - bnm[tid] * s;
    }

    const int wm = wid & 1, wn = wid >> 1;
    const int m  = wm*32 + lane;
    const int p  = blockIdx.x*64 + m;
    const int b  = p / NPIX;
    const int r  = p - b*NPIX;
    const int ho = r / WO, wo = r - (r/WO)*WO;
    const float* xb = x + (size_t)b * 96 * H_IN * W_IN;
    const int kkb = (wid >> 1) * 8;

    const int brow = wid*2 + (lane >> 4);
    const int kk2  = lane & 15;

    unsigned* sAhi = (unsigned*)(smem + A_HI);
    unsigned* sAlo = (unsigned*)(smem + A_LO);
    unsigned* sBhi = (unsigned*)(smem + B_HI);
    unsigned* sBlo = (unsigned*)(smem + B_LO);

    const unsigned aHiB = sb + A_HI + ((wm*32 + (lane&15))*40 + (lane>>4)*8)*2;
    const unsigned aLoB = aHiB + (A_LO - A_HI);
    const unsigned bHiB = sb + B_HI + ((wn*48 + (lane&15))*40 + (lane>>4)*8)*2;
    const unsigned bLoB = bHiB + (B_LO - B_HI);

    float acc[2][6][4];
    #pragma unroll
    for (int f = 0; f < 2; ++f)
        #pragma unroll
        for (int g = 0; g < 6; ++g)
            #pragma unroll
            for (int i = 0; i < 4; ++i) acc[f][g][i] = 0.f;

    float  av[8];
    float2 bv[12];

    {
        int ih = 2*ho - 1, iw = 2*wo - 1;
        bool ok = (ih >= 0) && (iw >= 0);
        const float* ptr = xb + ((size_t)kkb*H_IN + ih)*W_IN + iw;
        #pragma unroll
        for (int j = 0; j < 8; ++j)
            av[j] = ok ? __ldg(ptr + (size_t)j*H_IN*W_IN) : 0.f;
        #pragma unroll
        for (int i = 0; i < 12; ++i)
            bv[i] = __ldg((const float2*)(wr + (size_t)(brow + i*16)*864 + kk2*2));
    }

    for (int c = 0; c < 27; ++c) {
        {
            int wbase = m*20 + (kkb >> 1);
            #pragma unroll
            for (int jj = 0; jj < 4; ++jj) {
                float v0 = av[2*jj], v1 = av[2*jj+1];
                unsigned short h0 = bf16hi(v0), h1 = bf16hi(v1);
                unsigned short l0 = bf16hi(v0 - bf16f(h0));
                unsigned short l1 = bf16hi(v1 - bf16f(h1));
                sAhi[wbase + jj] = pack2(h0, h1);
                sAlo[wbase + jj] = pack2(l0, l1);
            }
            #pragma unroll
            for (int i = 0; i < 12; ++i) {
                int row = brow + i*16;
                float v0 = bv[i].x, v1 = bv[i].y;
                unsigned short h0 = bf16hi(v0), h1 = bf16hi(v1);
                unsigned short l0 = bf16hi(v0 - bf16f(h0));
                unsigned short l1 = bf16hi(v1 - bf16f(h1));
                sBhi[row*20 + kk2] = pack2(h0, h1);
                sBlo[row*20 + kk2] = pack2(l0, l1);
            }
        }
        __syncthreads();

        if (c < 26) {
            int cn = c + 1;
            int tap = cn / 3;
            int ic0 = (cn - tap*3)*32 + kkb;
            int ki = tap / 3, kj = tap - ki*3;
            int ih = 2*ho - 1 + ki, iw = 2*wo - 1 + kj;
            bool ok = (ih >= 0) && (iw >= 0);
            const float* ptr = xb + ((size_t)ic0*H_IN + ih)*W_IN + iw;
            #pragma unroll
            for (int j = 0; j < 8; ++j)
                av[j] = ok ? __ldg(ptr + (size_t)j*H_IN*W_IN) : 0.f;
            #pragma unroll
            for (int i = 0; i < 12; ++i)
                bv[i] = __ldg((const float2*)(wr + (size_t)(brow + i*16)*864 + cn*32 + kk2*2));
        }

        #pragma unroll
        for (int kst = 0; kst < 2; ++kst) {
            unsigned ko = kst*32;
            unsigned ah[2][4], al[2][4];
            ldm4(ah[0], aHiB + ko);
            ldm4(ah[1], aHiB + 1280 + ko);
            ldm4(al[0], aLoB + ko);
            ldm4(al[1], aLoB + 1280 + ko);
            #pragma unroll
            for (int g2 = 0; g2 < 3; ++g2) {
                unsigned bh[4], bl[4];
                ldm4(bh, bHiB + g2*1280 + ko);
                ldm4(bl, bLoB + g2*1280 + ko);
                #pragma unroll
                for (int f = 0; f < 2; ++f) {
                    mma_bf16(acc[f][2*g2],   ah[f], bh[0], bh[2]);
                    mma_bf16(acc[f][2*g2+1], ah[f], bh[1], bh[3]);
                    mma_bf16(acc[f][2*g2],   ah[f], bl[0], bl[2]);
                    mma_bf16(acc[f][2*g2+1], ah[f], bl[1], bl[3]);
                    mma_bf16(acc[f][2*g2],   al[f], bh[0], bh[2]);
                    mma_bf16(acc[f][2*g2+1], al[f], bh[1], bh[3]);
                }
            }
        }
        __syncthreads();
    }

    float* sEpi = (float*)(smem + 1536);
    #pragma unroll
    for (int f = 0; f < 2; ++f) {
        int row0 = wm*32 + f*16 + (lane >> 2);
        #pragma unroll
        for (int g = 0; g < 6; ++g) {
            int col0 = wn*48 + g*8 + 2*(lane & 3);
            float s0 = sbn[col0],     b0v = sbn[192 + col0];
            float s1 = sbn[col0 + 1], b1v = sbn[192 + col0 + 1];
            float v;
            v = acc[f][g][0]*s0 + b0v; v = v >= 0.f ? v : 0.1f*v; sEpi[ row0   *193 + col0  ] = v;
            v = acc[f][g][1]*s1 + b1v; v = v >= 0.f ? v : 0.1f*v; sEpi[ row0   *193 + col0+1] = v;
            v = acc[f][g][2]*s0 + b0v; v = v >= 0.f ? v : 0.1f*v; sEpi[(row0+8)*193 + col0  ] = v;
            v = acc[f][g][3]*s1 + b1v; v = v >= 0.f ? v : 0.1f*v; sEpi[(row0+8)*193 + col0+1] = v;
        }
    }
    __syncthreads();

    int p0 = blockIdx.x*64;
    int bb = p0 / NPIX;
    int rb = p0 - bb*NPIX;
    #pragma unroll 4
    for (int i = 0; i < 48; ++i) {
        int idx = tid + i*256;
        int mm = idx & 63, oc = idx >> 6;
        y[((size_t)bb*192 + oc)*NPIX + rb + mm] = sEpi[mm*193 + oc];
    }
}

// ===================== gwc mask: MMA conv 1x1 + fused softmax ================
// CTA: 128 pixels x 144 oc, K=192 in 6 chunks of 32. Warp w owns rows 16w..16w+15,
// all 144 cols (18 n8 frags). 3-pass bf16 split. Softmax fused via smem.
#define MKA_HI 0
#define MKA_LO 10240
#define MKB_HI 20480
#define MKB_LO 32000
#define SMEM_MASK (128*145*4)   // 74240 (sC overlays staging after last MMA)

__global__ __launch_bounds__(256, 1) void mask_mma_gwc(
    const float* __restrict__ y1, const float* __restrict__ w2,
    float* __restrict__ mask)
{
    extern __shared__ char smem[];
    const unsigned sb = smem_u32(smem);
    const int tid = threadIdx.x;
    const int wid = tid >> 5, lane = tid & 31;
    const int p0 = blockIdx.x * 128;
    const int b  = p0 / NPIX;
    const int pp = p0 - b*NPIX;
    const float* yb = y1 + (size_t)b*192*NPIX + pp;

    unsigned* sAhi = (unsigned*)(smem + MKA_HI);
    unsigned* sAlo = (unsigned*)(smem + MKA_LO);
    unsigned* sBhi = (unsigned*)(smem + MKB_HI);
    unsigned* sBlo = (unsigned*)(smem + MKB_LO);

    // gather mappings
    const int am  = tid & 127, ahb = tid >> 7;      // A: pixel row, k-pair phase
    const int brB = tid >> 4,  bq  = tid & 15;      // B: row base, k-pair

    // ldmatrix bases (stride 40 halves = 80B rows)
    const unsigned aB = sb + MKA_HI + ((wid*16 + (lane&15))*40 + (lane>>4)*8)*2;
    const unsigned bB = sb + MKB_HI + (((lane&15))*40 + (lane>>4)*8)*2;

    float acc[18][4];
    #pragma unroll
    for (int j = 0; j < 18; ++j)
        #pragma unroll
        for (int i = 0; i < 4; ++i) acc[j][i] = 0.f;

    float  av[16];
    float2 bv[9];

    // prefetch chunk 0
    #pragma unroll
    for (int i = 0; i < 8; ++i) {
        int q = ahb + 2*i;
        av[2*i]   = __ldg(yb + (size_t)(2*q)  *NPIX + am);
        av[2*i+1] = __ldg(yb + (size_t)(2*q+1)*NPIX + am);
    }
    #pragma unroll
    for (int i = 0; i < 9; ++i)
        bv[i] = __ldg((const float2*)(w2 + (size_t)(brB + 16*i)*192 + 2*bq));

    for (int c = 0; c < 6; ++c) {
        // convert + STS
        #pragma unroll
        for (int i = 0; i < 8; ++i) {
            int q = ahb + 2*i;
            float v0 = av[2*i], v1 = av[2*i+1];
            unsigned short h0 = bf16hi(v0), h1 = bf16hi(v1);
            unsigned short l0 = bf16hi(v0 - bf16f(h0));
            unsigned short l1 = bf16hi(v1 - bf16f(h1));
            sAhi[am*20 + q] = pack2(h0, h1);
            sAlo[am*20 + q] = pack2(l0, l1);
        }
        #pragma unroll
        for (int i = 0; i < 9; ++i) {
            int row = brB + 16*i;
            float v0 = bv[i].x, v1 = bv[i].y;
            unsigned short h0 = bf16hi(v0), h1 = bf16hi(v1);
            unsigned short l0 = bf16hi(v0 - bf16f(h0));
            unsigned short l1 = bf16hi(v1 - bf16f(h1));
            sBhi[row*20 + bq] = pack2(h0, h1);
            sBlo[row*20 + bq] = pack2(l0, l1);
        }
        __syncthreads();

        // prefetch next chunk
        if (c < 5) {
            int kb = (c + 1) * 32;
            #pragma unroll
            for (int i = 0; i < 8; ++i) {
                int q = ahb + 2*i;
                av[2*i]   = __ldg(yb + (size_t)(kb + 2*q)  *NPIX + am);
                av[2*i+1] = __ldg(yb + (size_t)(kb + 2*q+1)*NPIX + am);
            }
            #pragma unroll
            for (int i = 0; i < 9; ++i)
                bv[i] = __ldg((const float2*)(w2 + (size_t)(brB + 16*i)*192 + kb + 2*bq));
        }

        // MMA
        #pragma unroll
        for (int ks = 0; ks < 2; ++ks) {
            unsigned ko = ks*32;
            unsigned ah[4], al[4];
            ldm4(ah, aB + ko);
            ldm4(al, aB + (MKA_LO - MKA_HI) + ko);
            #pragma unroll
            for (int jp = 0; jp < 9; ++jp) {
                unsigned bh[4], bl[4];
                ldm4(bh, bB + jp*1280 + ko);
                ldm4(bl, bB + (MKB_LO - MKB_HI) + jp*1280 + ko);
                mma_bf16(acc[2*jp],   ah, bh[0], bh[2]);
                mma_bf16(acc[2*jp+1], ah, bh[1], bh[3]);
                mma_bf16(acc[2*jp],   ah, bl[0], bl[2]);
                mma_bf16(acc[2*jp+1], ah, bl[1], bl[3]);
                mma_bf16(acc[2*jp],   al, bh[0], bh[2]);
                mma_bf16(acc[2*jp+1], al, bh[1], bh[3]);
            }
        }
        __syncthreads();
    }

    // ---- store logits to smem (overlays staging; all MMAs done) ----
    float* sC = (float*)smem;
    {
        int r0 = wid*16 + (lane >> 2);
        #pragma unroll
        for (int j = 0; j < 18; ++j) {
            int c0 = j*8 + 2*(lane & 3);
            sC[ r0   *145 + c0  ] = acc[j][0];
            sC[ r0   *145 + c0+1] = acc[j][1];
            sC[(r0+8)*145 + c0  ] = acc[j][2];
            sC[(r0+8)*145 + c0+1] = acc[j][3];
        }
    }
    __syncthreads();

    // ---- softmax over 9 per (pixel, group), coalesced store ----
    const int sm = tid & 127;
    const float* srow = sC + sm*145;
    #pragma unroll
    for (int gi = 0; gi < 8; ++gi) {
        int g = (tid >> 7)*8 + gi;
        float v[9];
        #pragma unroll
        for (int j = 0; j < 9; ++j) v[j] = srow[g*9 + j];
        float mx = v[0];
        #pragma unroll
        for (int j = 1; j < 9; ++j) mx = fmaxf(mx, v[j]);
        float e[9], sum = 0.f;
        #pragma unroll
        for (int j = 0; j < 9; ++j) { e[j] = __expf(v[j] - mx); sum += e[j]; }
        float rs = 1.f / sum;
        float* mrow = mask + ((size_t)b*144 + g*9)*NPIX + pp + sm;
        #pragma unroll
        for (int j = 0; j < 9; ++j) mrow[(size_t)j*NPIX] = e[j]*rs;
    }
}

// ------------------- conv 3x3 stride2 pad1 + BN + leaky (fp32, cat path) -----
template<int CIN, int CMID, int OC_PB>
__global__ __launch_bounds__(64) void conv1_bn_lrelu(
    const float* __restrict__ x, const float* __restrict__ w,
    const float* __restrict__ bng, const float* __restrict__ bnb,
    const float* __restrict__ bnm, const float* __restrict__ bnv,
    float* __restrict__ y)
{
    __shared__ float s_in[33*33];
    __shared__ float s_w[OC_PB*9];
    const int NOCG = CMID / OC_PB;
    int bz  = blockIdx.z;
    int b   = bz / NOCG, ocg = bz % NOCG;
    int oc0 = ocg * OC_PB;
    int ho0 = blockIdx.y * 16, wo0 = blockIdx.x * 16;
    int ih0 = 2*ho0 - 1, iw0 = 2*wo0 - 1;
    int tid = threadIdx.x;
    int ty  = tid >> 3, tx = tid & 7;

    int  goff[18]; bool gok[18]; bool wok[18];
    #pragma unroll
    for (int it = 0; it < 18; ++it) {
        int idx = tid + it*64;
        int r = idx / 33, c = idx - r*33;
        int ih = ih0 + r, iw = iw0 + c;
        wok[it] = idx < 1089;
        gok[it] = wok[it] && ih >= 0 && ih < H_IN && iw >= 0 && iw < W_IN;
        goff[it] = ih * W_IN + iw;
    }

    float acc[OC_PB][2][2];
    #pragma unroll
    for (int o = 0; o < OC_PB; ++o)
        #pragma unroll
        for (int a = 0; a < 2; ++a)
            #pragma unroll
            for (int d = 0; d < 2; ++d) acc[o][a][d] = 0.f;

    const float* xb = x + (long)b * CIN * H_IN * W_IN;
    for (int ic = 0; ic < CIN; ++ic) {
        const float* xc = xb + (long)ic * H_IN * W_IN;
        #pragma unroll
        for (int it = 0; it < 18; ++it) {
            int idx = tid + it*64;
            if (wok[it]) s_in[idx] = gok[it] ? __ldg(xc + goff[it]) : 0.f;
        }
        for (int i = tid; i < OC_PB*9; i += 64) {
            int oc = i / 9, j = i - oc*9;
            s_w[i] = w[((oc0 + oc)*CIN + ic)*9 + j];
        }
        __syncthreads();

        float v[5][5];
        #pragma unroll
        for (int r = 0; r < 5; ++r)
            #pragma unroll
            for (int c = 0; c < 5; ++c)
                v[r][c] = s_in[(4*ty + r)*33 + 4*tx + c];

        #pragma unroll
        for (int o = 0; o < OC_PB; ++o) {
            #pragma unroll
            for (int ki = 0; ki < 3; ++ki)
                #pragma unroll
                for (int kj = 0; kj < 3; ++kj) {
                    float wv = s_w[o*9 + ki*3 + kj];
                    acc[o][0][0] += wv * v[ki  ][kj  ];
                    acc[o][0][1] += wv * v[ki  ][kj+2];
                    acc[o][1][0] += wv * v[ki+2][kj  ];
                    acc[o][1][1] += wv * v[ki+2][kj+2];
                }
        }
        __syncthreads();
    }

    #pragma unroll
    for (int o = 0; o < OC_PB; ++o) {
        int oc = oc0 + o;
        float s    = bng[oc] * rsqrtf(bnv[oc] + EPSV);
        float bias = bnb[oc] - bnm[oc] * s;
        #pragma unroll
        for (int dy = 0; dy < 2; ++dy)
            #pragma unroll
            for (int dx = 0; dx < 2; ++dx) {
                int ho = ho0 + 2*ty + dy, wo = wo0 + 2*tx + dx;
                float vv = acc[o][dy][dx] * s + bias;
                vv = vv >= 0.f ? vv : 0.1f * vv;
                y[(long)(b*CMID + oc)*NPIX + ho*WO + wo] = vv;
            }
    }
}

// ------------------- 1x1 conv + softmax over 9 (scalar, cat path) ------------
template<int CMID, int G, int CK>
__global__ __launch_bounds__(G*8) void mask_softmax(
    const float* __restrict__ y1, const float* __restrict__ w2,
    float* __restrict__ mask)
{
    const int NT = G*8;
    __shared__ float s_y[CMID*32];
    __shared__ float s_w[G*9*(CK+1)];
    int b  = blockIdx.y;
    int p0 = blockIdx.x * 32;
    int tid = threadIdx.x;
    int g = tid >> 3, q = tid & 7;

    for (int i = tid; i < CMID*32; i += NT) {
        int k = i >> 5, p = i & 31;
        s_y[i] = y1[(long)(b*CMID + k)*NPIX + p0 + p];
    }

    float acc[9][4];
    #pragma unroll
    for (int j = 0; j < 9; ++j)
        #pragma unroll
        for (int i = 0; i < 4; ++i) acc[j][i] = 0.f;

    for (int c0 = 0; c0 < CMID; c0 += CK) {
        __syncthreads();
        for (int i = tid; i < G*9*CK; i += NT) {
            int oc = i / CK, kk = i - oc*CK;
            s_w[oc*(CK+1) + kk] = w2[oc*CMID + c0 + kk];
        }
        __syncthreads();
        #pragma unroll 4
        for (int kk = 0; kk < CK; ++kk) {
            float yv[4];
            #pragma unroll
            for (int i = 0; i < 4; ++i) yv[i] = s_y[(c0 + kk)*32 + q + 8*i];
            #pragma unroll
            for (int j = 0; j < 9; ++j) {
                float wv = s_w[(g*9 + j)*(CK+1) + kk];
                #pragma unroll
                for (int i = 0; i < 4; ++i) acc[j][i] += wv * yv[i];
            }
        }
    }

    #pragma unroll
    for (int i = 0; i < 4; ++i) {
        float m = acc[0][i];
        #pragma unroll
        for (int j = 1; j < 9; ++j) m = fmaxf(m, acc[j][i]);
        float e[9], sum = 0.f;
        #pragma unroll
        for (int j = 0; j < 9; ++j) { e[j] = __expf(acc[j][i] - m); sum += e[j]; }
        float rs = 1.f / sum;
        #pragma unroll
        for (int j = 0; j < 9; ++j)
            mask[(long)(b*G*9 + g*9 + j)*NPIX + p0 + q + 8*i] = e[j] * rs;
    }
}

// ------------------- unfold-weighted-sum aggregation -------------------------
template<int C, int GROUPS>
__global__ __launch_bounds__(256) void aggregate(
    const float* __restrict__ x, const float* __restrict__ mask,
    float* __restrict__ out)
{
    int idx = blockIdx.x * blockDim.x + threadIdx.x;
    if (idx >= BATCH*C*NPIX) return;
    int wo = idx % WO;
    int t  = idx / WO;
    int ho = t % HO; t /= HO;
    int c  = t % C;
    int b  = t / C;
    int g  = c % GROUPS;

    const float* xb = x + (long)(b*C + c) * H_IN * W_IN;
    const float* mb = mask + (long)(b*GROUPS*9 + g*9) * NPIX + ho*WO + wo;

    float acc = 0.f;
    #pragma unroll
    for (int ki = 0; ki < 3; ++ki) {
        int ih = 2*ho - 1 + ki;
        bool okh = (ih >= 0) && (ih < H_IN);
        #pragma unroll
        for (int kj = 0; kj < 3; ++kj) {
            int iw = 2*wo - 1 + kj;
            float xv = (okh && iw >= 0 && iw < W_IN) ? __ldg(xb + ih*W_IN + iw) : 0.f;
            acc += __ldg(mb + (ki*3 + kj)*NPIX) * xv;
        }
    }
    out[idx] = acc;
}

// ------------------- group-wise correlation volume ---------------------------
__global__ __launch_bounds__(128) void vol_gwc(const float* __restrict__ g8,
                                               float* __restrict__ out)
{
    int idx = blockIdx.x * blockDim.x + threadIdx.x;
    int w  = idx % WO;
    int t  = idx / WO;
    int h  = t % HO; t /= HO;
    int g  = t % 8;
    int b2 = t / 8;

    const float* lp = g8 + (long)(b2*96 + g*12) * NPIX + h*WO + w;
    const float* rp = g8 + (long)((b2+2)*96 + g*12) * NPIX + h*WO;
    float lv[12];
    #pragma unroll
    for (int c = 0; c < 12; ++c) lv[c] = lp[c*NPIX];

    float* ob = out + (long)(b2*32 + g) * DISP * NPIX + h*WO + w;
    for (int d = 0; d < DISP; ++d) {
        float val = 0.f;
        if (d <= w) {
            float s = 0.f;
            #pragma unroll
            for (int c = 0; c < 12; ++c) s += lv[c] * __ldg(rp + c*NPIX + (w - d));
            val = s * (1.f/12.f);
        }
        ob[(long)d*NPIX] = val;
    }
}

// ------------------- concat volume -------------------------------------------
__global__ __launch_bounds__(256) void vol_cat(const float* __restrict__ c8,
                                               float* __restrict__ out)
{
    int idx = blockIdx.x * blockDim.x + threadIdx.x;
    int w  = idx % WO;
    int t  = idx / WO;
    int h  = t % HO; t /= HO;
    int d  = t % DISP; t /= DISP;
    int ch = t % 24;
    int b2 = t / 24;

    float val = 0.f;
    if (w >= d) {
        if (ch < 12)
            val = __ldg(c8 + (long)(b2*12 + ch) * NPIX + h*WO + w);
        else
            val = __ldg(c8 + (long)((b2+2)*12 + (ch-12)) * NPIX + h*WO + (w - d));
    }
    out[(long)(b2*32 + 8 + ch) * DISP * NPIX + (long)d*NPIX + h*WO + w] = val;
}

// ------------------- launch --------------------------------------------------
extern "C" void kernel_launch(void* const* d_in, const int* in_sizes, int n_in,
                              void* d_out, int out_size)
{
    const float* gwc_f = (const float*)d_in[0];
    const float* cat_f = (const float*)d_in[1];
    const float* g_w1  = (const float*)d_in[2];
    const float* g_bg  = (const float*)d_in[3];
    const float* g_bb  = (const float*)d_in[4];
    const float* g_bm  = (const float*)d_in[5];
    const float* g_bv  = (const float*)d_in[6];
    const float* g_w2  = (const float*)d_in[7];
    const float* c_w1  = (const float*)d_in[8];
    const float* c_bg  = (const float*)d_in[9];
    const float* c_bb  = (const float*)d_in[10];
    const float* c_bm  = (const float*)d_in[11];
    const float* c_bv  = (const float*)d_in[12];
    const float* c_w2  = (const float*)d_in[13];
    float* out = (float*)d_out;

    float *y1g, *y1c, *mg, *mc, *g8, *c8, *wr;
    cudaGetSymbolAddress((void**)&y1g, g_y1g);
    cudaGetSymbolAddress((void**)&y1c, g_y1c);
    cudaGetSymbolAddress((void**)&mg,  g_mg);
    cudaGetSymbolAddress((void**)&mc,  g_mc);
    cudaGetSymbolAddress((void**)&g8,  g_g8);
    cudaGetSymbolAddress((void**)&c8,  g_c8);
    cudaGetSymbolAddress((void**)&wr,  g_wr);

    // 0) weight reorder for tensorized conv1
    wreorder<<<648, 256>>>(g_w1, wr);

    // 1) conv1 + BN + leaky
    cudaFuncSetAttribute(conv1_gwc_mma, cudaFuncAttributeMaxDynamicSharedMemorySize, SMEM_CONV1);
    conv1_gwc_mma<<<720, 256, SMEM_CONV1>>>(gwc_f, wr, g_bg, g_bb, g_bm, g_bv, y1g);
    conv1_bn_lrelu<12, 24, 8><<<dim3(9,5,BATCH*3), 64>>>(cat_f, c_w1, c_bg, c_bb, c_bm, c_bv, y1c);

    // 2) 1x1 conv + softmax masks (gwc path tensorized)
    cudaFuncSetAttribute(mask_mma_gwc, cudaFuncAttributeMaxDynamicSharedMemorySize, SMEM_MASK);
    mask_mma_gwc<<<360, 256, SMEM_MASK>>>(y1g, g_w2, mg);
    mask_softmax<24,12,24><<<dim3(360,BATCH), 96>>>(y1c, c_w2, mc);

    // 3) adaptive aggregation
    aggregate<96,16><<<(BATCH*96*NPIX)/256, 256>>>(gwc_f, mg, g8);
    aggregate<12,12><<<(BATCH*12*NPIX)/256, 256>>>(cat_f, mc, c8);

    // 4) cost volumes into output
    vol_gwc<<<(2*8*NPIX)/128, 128>>>(g8, out);
    vol_cat<<<(2*24*DISP*NPIX)/256, 256>>>(c8, out);
}

// round 5
// speedup vs baseline: 2.2942x; 1.1135x over previous
#include <cuda_runtime.h>
#include <cstdint>

#define H_IN 160
#define W_IN 288
#define HO   80
#define WO   144
#define NPIX (HO*WO)          // 11520
#define BATCH 4
#define EPSV 1e-5f
#define DISP 24

// ------------------- scratch (static device memory, no allocs) ---------------
__device__ float g_y1g[BATCH*192*NPIX];   // gwc conv1+bn+lrelu out
__device__ float g_y1c[BATCH*24*NPIX];    // cat conv1+bn+lrelu out
__device__ float g_mg [BATCH*144*NPIX];   // gwc softmax mask
__device__ float g_mc [BATCH*108*NPIX];   // cat softmax mask
__device__ float g_g8 [BATCH*96*NPIX];    // gwc downsampled features
__device__ float g_c8 [BATCH*12*NPIX];    // cat downsampled features
__device__ unsigned g_wc1hi[27*192*16];   // conv1 weights, packed bf16 hi, staging order
__device__ unsigned g_wc1lo[27*192*16];   // conv1 weights, packed bf16 lo
__device__ unsigned g_w2hi [6*144*16];    // mask weights, packed bf16 hi
__device__ unsigned g_w2lo [6*144*16];    // mask weights, packed bf16 lo

// ===================== small helpers ========================================
__device__ __forceinline__ unsigned smem_u32(const void* p){
    unsigned a;
    asm("{ .reg .u64 t; cvta.to.shared.u64 t, %1; cvt.u32.u64 %0, t; }"
        : "=r"(a) : "l"(p));
    return a;
}
__device__ __forceinline__ unsigned short bf16hi(float x){
    unsigned u = __float_as_uint(x);
    unsigned r = u + 0x7fffu + ((u >> 16) & 1u);
    return (unsigned short)(r >> 16);
}
__device__ __forceinline__ float bf16f(unsigned short h){
    return __uint_as_float(((unsigned)h) << 16);
}
__device__ __forceinline__ unsigned pack2(unsigned short a, unsigned short b){
    return (unsigned)a | ((unsigned)b << 16);
}
__device__ __forceinline__ void ldm4(unsigned* r, unsigned addr){
    asm volatile("ldmatrix.sync.aligned.m8n8.x4.shared.b16 {%0,%1,%2,%3}, [%4];"
        : "=r"(r[0]), "=r"(r[1]), "=r"(r[2]), "=r"(r[3]) : "r"(addr));
}
__device__ __forceinline__ void mma_bf16(float* c, const unsigned* a,
                                         unsigned b0, unsigned b1){
    asm volatile("mma.sync.aligned.m16n8k16.row.col.f32.bf16.bf16.f32 "
        "{%0,%1,%2,%3}, {%4,%5,%6,%7}, {%8,%9}, {%0,%1,%2,%3};"
        : "+f"(c[0]), "+f"(c[1]), "+f"(c[2]), "+f"(c[3])
        : "r"(a[0]), "r"(a[1]), "r"(a[2]), "r"(a[3]), "r"(b0), "r"(b1));
}

// ===================== weight prep (packed bf16 hi/lo, staging layout) =======
// conv1: k = tap*96 + ic ordering; entry (c, row, kk) packs k = c*32+2kk, +1.
__global__ __launch_bounds__(256) void wprep_conv1(const float* __restrict__ w,
                                                   unsigned* __restrict__ whi,
                                                   unsigned* __restrict__ wlo)
{
    int idx = blockIdx.x * 256 + threadIdx.x;          // 27*192*16 = 82944
    if (idx >= 27*192*16) return;
    int kk = idx & 15;
    int row = (idx >> 4) % 192;
    int c   = idx / (192*16);
    int k0 = c*32 + 2*kk, k1 = k0 + 1;
    int tap0 = k0 / 96, ic0 = k0 - tap0*96;
    int tap1 = k1 / 96, ic1 = k1 - tap1*96;
    float v0 = w[row*864 + ic0*9 + tap0];
    float v1 = w[row*864 + ic1*9 + tap1];
    unsigned short h0 = bf16hi(v0), h1 = bf16hi(v1);
    whi[idx] = pack2(h0, h1);
    wlo[idx] = pack2(bf16hi(v0 - bf16f(h0)), bf16hi(v1 - bf16f(h1)));
}

__global__ __launch_bounds__(256) void wprep_mask(const float* __restrict__ w2,
                                                  unsigned* __restrict__ whi,
                                                  unsigned* __restrict__ wlo)
{
    int idx = blockIdx.x * 256 + threadIdx.x;          // 6*144*16 = 13824
    if (idx >= 6*144*16) return;
    int kk = idx & 15;
    int row = (idx >> 4) % 144;
    int c   = idx / (144*16);
    int k0 = c*32 + 2*kk;
    float v0 = w2[row*192 + k0];
    float v1 = w2[row*192 + k0 + 1];
    unsigned short h0 = bf16hi(v0), h1 = bf16hi(v1);
    whi[idx] = pack2(h0, h1);
    wlo[idx] = pack2(bf16hi(v0 - bf16f(h0)), bf16hi(v1 - bf16f(h1)));
}

// ===================== conv1 gwc: implicit GEMM on mma.sync bf16 =============
// CTA: M=128 pixels x N=192 oc, K=864 in 27 chunks of 32 (k = tap*96+ic).
// 3-pass bf16 split. Warps 2x4: wm -> 64 rows, wn -> 48 cols. acc[4][6][4].
#define C1_A_HI 1536
#define C1_A_LO (C1_A_HI + 10240)
#define C1_B_HI (C1_A_LO + 10240)
#define C1_B_LO (C1_B_HI + 15360)
#define SMEM_CONV1 (C1_B_LO + 15360)   // 52736; epi 64x193x4 overlays staging

__global__ __launch_bounds__(256, 1) void conv1_gwc_mma(
    const float* __restrict__ x,
    const unsigned* __restrict__ whi, const unsigned* __restrict__ wlo,
    const float* __restrict__ bng, const float* __restrict__ bnb,
    const float* __restrict__ bnm, const float* __restrict__ bnv,
    float* __restrict__ y)
{
    extern __shared__ char smem[];
    const unsigned sb = smem_u32(smem);
    const int tid = threadIdx.x;
    const int wid = tid >> 5, lane = tid & 31;
    float* sbn = (float*)smem;

    if (tid < 192) {
        float s = bng[tid] * rsqrtf(bnv[tid] + EPSV);
        sbn[tid] = s;
        sbn[192 + tid] = bnb[tid] - bnm[tid] * s;
    }

    // ---- A gather geometry: 2 threads per pixel row, 16 ic each ----
    const int m = tid & 127;
    const int khalf = tid >> 7;
    const int p  = blockIdx.x*128 + m;
    const int b  = p / NPIX;
    const int r  = p - b*NPIX;
    const int ho = r / WO, wo = r - (r/WO)*WO;
    const float* xb = x + (size_t)b * 96 * H_IN * W_IN;

    // ---- B copy geometry: 4 threads per row, uint4 each ----
    const int brow4 = tid >> 2, bq4 = (tid & 3)*4;

    // ---- warp tiling ----
    const int wm = wid & 1, wn = wid >> 1;
    const unsigned aHiB = sb + C1_A_HI + ((wm*64 + (lane&15))*40 + (lane>>4)*8)*2;
    const unsigned aLoB = aHiB + 10240;
    const unsigned bHiB = sb + C1_B_HI + ((wn*48 + (lane&15))*40 + (lane>>4)*8)*2;
    const unsigned bLoB = bHiB + 15360;

    unsigned* sAhi = (unsigned*)(smem + C1_A_HI);
    unsigned* sAlo = (unsigned*)(smem + C1_A_LO);

    float acc[4][6][4];
    #pragma unroll
    for (int f = 0; f < 4; ++f)
        #pragma unroll
        for (int g = 0; g < 6; ++g)
            #pragma unroll
            for (int i = 0; i < 4; ++i) acc[f][g][i] = 0.f;

    float av[16];
    uint4 bhv[3], blv[3];

    // prefetch chunk 0
    {
        int ih = 2*ho - 1, iw = 2*wo - 1;
        bool ok = (ih >= 0) && (iw >= 0);
        const float* ptr = xb + ((size_t)(khalf*16)*H_IN + ih)*W_IN + iw;
        #pragma unroll
        for (int j = 0; j < 16; ++j)
            av[j] = ok ? __ldg(ptr + (size_t)j*H_IN*W_IN) : 0.f;
        #pragma unroll
        for (int it = 0; it < 3; ++it) {
            int e = (brow4 + it*64)*16 + bq4;
            bhv[it] = __ldg((const uint4*)(whi + e));
            blv[it] = __ldg((const uint4*)(wlo + e));
        }
    }

    for (int c = 0; c < 27; ++c) {
        // ---- STS A (convert) + B (copy) ----
        {
            int wbase = m*20 + khalf*8;
            #pragma unroll
            for (int jj = 0; jj < 8; ++jj) {
                float v0 = av[2*jj], v1 = av[2*jj+1];
                unsigned short h0 = bf16hi(v0), h1 = bf16hi(v1);
                unsigned short l0 = bf16hi(v0 - bf16f(h0));
                unsigned short l1 = bf16hi(v1 - bf16f(h1));
                sAhi[wbase + jj] = pack2(h0, h1);
                sAlo[wbase + jj] = pack2(l0, l1);
            }
            #pragma unroll
            for (int it = 0; it < 3; ++it) {
                int so = ((brow4 + it*64)*20 + bq4)*4;
                *(uint4*)(smem + C1_B_HI + so) = bhv[it];
                *(uint4*)(smem + C1_B_LO + so) = blv[it];
            }
        }
        __syncthreads();

        // ---- prefetch next chunk ----
        if (c < 26) {
            int cn = c + 1;
            int tap = cn / 3;
            int ic0 = (cn - tap*3)*32 + khalf*16;
            int ki = tap / 3, kj = tap - ki*3;
            int ih = 2*ho - 1 + ki, iw = 2*wo - 1 + kj;
            bool ok = (ih >= 0) && (iw >= 0);
            const float* ptr = xb + ((size_t)ic0*H_IN + ih)*W_IN + iw;
            #pragma unroll
            for (int j = 0; j < 16; ++j)
                av[j] = ok ? __ldg(ptr + (size_t)j*H_IN*W_IN) : 0.f;
            #pragma unroll
            for (int it = 0; it < 3; ++it) {
                int e = (cn*192 + brow4 + it*64)*16 + bq4;
                bhv[it] = __ldg((const uint4*)(whi + e));
                blv[it] = __ldg((const uint4*)(wlo + e));
            }
        }

        // ---- MMA ----
        #pragma unroll
        for (int kst = 0; kst < 2; ++kst) {
            unsigned ko = kst*32;
            unsigned ah[4][4], al[4][4];
            #pragma unroll
            for (int f = 0; f < 4; ++f) {
                ldm4(ah[f], aHiB + f*1280 + ko);
                ldm4(al[f], aLoB + f*1280 + ko);
            }
            #pragma unroll
            for (int g2 = 0; g2 < 3; ++g2) {
                unsigned bh[4], bl[4];
                ldm4(bh, bHiB + g2*1280 + ko);
                ldm4(bl, bLoB + g2*1280 + ko);
                #pragma unroll
                for (int f = 0; f < 4; ++f) {
                    mma_bf16(acc[f][2*g2],   ah[f], bh[0], bh[2]);
                    mma_bf16(acc[f][2*g2+1], ah[f], bh[1], bh[3]);
                    mma_bf16(acc[f][2*g2],   ah[f], bl[0], bl[2]);
                    mma_bf16(acc[f][2*g2+1], ah[f], bl[1], bl[3]);
                    mma_bf16(acc[f][2*g2],   al[f], bh[0], bh[2]);
                    mma_bf16(acc[f][2*g2+1], al[f], bh[1], bh[3]);
                }
            }
        }
        __syncthreads();
    }

    // ---- epilogue: two 64-row transpose passes (reuses staging smem) ----
    float* sEpi = (float*)(smem + C1_A_HI);
    #pragma unroll
    for (int half = 0; half < 2; ++half) {
        if (wm == half) {
            #pragma unroll
            for (int f = 0; f < 4; ++f) {
                int row0 = f*16 + (lane >> 2);
                #pragma unroll
                for (int g = 0; g < 6; ++g) {
                    int col0 = wn*48 + g*8 + 2*(lane & 3);
                    float s0 = sbn[col0],     b0v = sbn[192 + col0];
                    float s1 = sbn[col0 + 1], b1v = sbn[192 + col0 + 1];
                    float v;
                    v = acc[f][g][0]*s0 + b0v; v = v >= 0.f ? v : 0.1f*v; sEpi[ row0   *193 + col0  ] = v;
                    v = acc[f][g][1]*s1 + b1v; v = v >= 0.f ? v : 0.1f*v; sEpi[ row0   *193 + col0+1] = v;
                    v = acc[f][g][2]*s0 + b0v; v = v >= 0.f ? v : 0.1f*v; sEpi[(row0+8)*193 + col0  ] = v;
                    v = acc[f][g][3]*s1 + b1v; v = v >= 0.f ? v : 0.1f*v; sEpi[(row0+8)*193 + col0+1] = v;
                }
            }
        }
        __syncthreads();
        int p0 = blockIdx.x*128 + half*64;
        int bb = p0 / NPIX;
        int rb = p0 - bb*NPIX;
        #pragma unroll 4
        for (int i = 0; i < 48; ++i) {
            int idx = tid + i*256;
            int mm = idx & 63, oc = idx >> 6;
            y[((size_t)bb*192 + oc)*NPIX + rb + mm] = sEpi[mm*193 + oc];
        }
        __syncthreads();
    }
}

// ===================== gwc mask: MMA conv 1x1 + fused softmax ================
#define MKA_HI 0
#define MKA_LO 10240
#define MKB_HI 20480
#define MKB_LO 32000
#define SMEM_MASK (128*145*4)   // 74240

__global__ __launch_bounds__(256, 1) void mask_mma_gwc(
    const float* __restrict__ y1,
    const unsigned* __restrict__ whi, const unsigned* __restrict__ wlo,
    float* __restrict__ mask)
{
    extern __shared__ char smem[];
    const unsigned sb = smem_u32(smem);
    const int tid = threadIdx.x;
    const int wid = tid >> 5, lane = tid & 31;
    const int p0 = blockIdx.x * 128;
    const int b  = p0 / NPIX;
    const int pp = p0 - b*NPIX;
    const float* yb = y1 + (size_t)b*192*NPIX + pp;

    unsigned* sAhi = (unsigned*)(smem + MKA_HI);
    unsigned* sAlo = (unsigned*)(smem + MKA_LO);

    const int am  = tid & 127, ahb = tid >> 7;
    const int brow4 = tid >> 2, bq4 = (tid & 3)*4;

    const unsigned aB = sb + MKA_HI + ((wid*16 + (lane&15))*40 + (lane>>4)*8)*2;
    const unsigned bB = sb + MKB_HI + (((lane&15))*40 + (lane>>4)*8)*2;

    float acc[18][4];
    #pragma unroll
    for (int j = 0; j < 18; ++j)
        #pragma unroll
        for (int i = 0; i < 4; ++i) acc[j][i] = 0.f;

    float av[16];
    uint4 bhv[3], blv[3];

    // prefetch chunk 0
    #pragma unroll
    for (int i = 0; i < 8; ++i) {
        int q = ahb + 2*i;
        av[2*i]   = __ldg(yb + (size_t)(2*q)  *NPIX + am);
        av[2*i+1] = __ldg(yb + (size_t)(2*q+1)*NPIX + am);
    }
    #pragma unroll
    for (int it = 0; it < 3; ++it) {
        int row = brow4 + it*64;
        if (row < 144) {
            int e = row*16 + bq4;
            bhv[it] = __ldg((const uint4*)(whi + e));
            blv[it] = __ldg((const uint4*)(wlo + e));
        }
    }

    for (int c = 0; c < 6; ++c) {
        // STS A (convert) + B (copy)
        #pragma unroll
        for (int i = 0; i < 8; ++i) {
            int q = ahb + 2*i;
            float v0 = av[2*i], v1 = av[2*i+1];
            unsigned short h0 = bf16hi(v0), h1 = bf16hi(v1);
            unsigned short l0 = bf16hi(v0 - bf16f(h0));
            unsigned short l1 = bf16hi(v1 - bf16f(h1));
            sAhi[am*20 + q] = pack2(h0, h1);
            sAlo[am*20 + q] = pack2(l0, l1);
        }
        #pragma unroll
        for (int it = 0; it < 3; ++it) {
            int row = brow4 + it*64;
            if (row < 144) {
                int so = (row*20 + bq4)*4;
                *(uint4*)(smem + MKB_HI + so) = bhv[it];
                *(uint4*)(smem + MKB_LO + so) = blv[it];
            }
        }
        __syncthreads();

        // prefetch next chunk
        if (c < 5) {
            int kb = (c + 1) * 32;
            #pragma unroll
            for (int i = 0; i < 8; ++i) {
                int q = ahb + 2*i;
                av[2*i]   = __ldg(yb + (size_t)(kb + 2*q)  *NPIX + am);
                av[2*i+1] = __ldg(yb + (size_t)(kb + 2*q+1)*NPIX + am);
            }
            #pragma unroll
            for (int it = 0; it < 3; ++it) {
                int row = brow4 + it*64;
                if (row < 144) {
                    int e = ((c+1)*144 + row)*16 + bq4;
                    bhv[it] = __ldg((const uint4*)(whi + e));
                    blv[it] = __ldg((const uint4*)(wlo + e));
                }
            }
        }

        // MMA
        #pragma unroll
        for (int ks = 0; ks < 2; ++ks) {
            unsigned ko = ks*32;
            unsigned ah[4], al[4];
            ldm4(ah, aB + ko);
            ldm4(al, aB + (MKA_LO - MKA_HI) + ko);
            #pragma unroll
            for (int jp = 0; jp < 9; ++jp) {
                unsigned bh[4], bl[4];
                ldm4(bh, bB + jp*1280 + ko);
                ldm4(bl, bB + (MKB_LO - MKB_HI) + jp*1280 + ko);
                mma_bf16(acc[2*jp],   ah, bh[0], bh[2]);
                mma_bf16(acc[2*jp+1], ah, bh[1], bh[3]);
                mma_bf16(acc[2*jp],   ah, bl[0], bl[2]);
                mma_bf16(acc[2*jp+1], ah, bl[1], bl[3]);
                mma_bf16(acc[2*jp],   al, bh[0], bh[2]);
                mma_bf16(acc[2*jp+1], al, bh[1], bh[3]);
            }
        }
        __syncthreads();
    }

    // store logits to smem
    float* sC = (float*)smem;
    {
        int r0 = wid*16 + (lane >> 2);
        #pragma unroll
        for (int j = 0; j < 18; ++j) {
            int c0 = j*8 + 2*(lane & 3);
            sC[ r0   *145 + c0  ] = acc[j][0];
            sC[ r0   *145 + c0+1] = acc[j][1];
            sC[(r0+8)*145 + c0  ] = acc[j][2];
            sC[(r0+8)*145 + c0+1] = acc[j][3];
        }
    }
    __syncthreads();

    // softmax over 9 per (pixel, group), coalesced store
    const int sm = tid & 127;
    const float* srow = sC + sm*145;
    #pragma unroll
    for (int gi = 0; gi < 8; ++gi) {
        int g = (tid >> 7)*8 + gi;
        float v[9];
        #pragma unroll
        for (int j = 0; j < 9; ++j) v[j] = srow[g*9 + j];
        float mx = v[0];
        #pragma unroll
        for (int j = 1; j < 9; ++j) mx = fmaxf(mx, v[j]);
        float e[9], sum = 0.f;
        #pragma unroll
        for (int j = 0; j < 9; ++j) { e[j] = __expf(v[j] - mx); sum += e[j]; }
        float rs = 1.f / sum;
        float* mrow = mask + ((size_t)b*144 + g*9)*NPIX + pp + sm;
        #pragma unroll
        for (int j = 0; j < 9; ++j) mrow[(size_t)j*NPIX] = e[j]*rs;
    }
}

// ------------------- conv 3x3 stride2 pad1 + BN + leaky (fp32, cat path) -----
template<int CIN, int CMID, int OC_PB>
__global__ __launch_bounds__(64) void conv1_bn_lrelu(
    const float* __restrict__ x, const float* __restrict__ w,
    const float* __restrict__ bng, const float* __restrict__ bnb,
    const float* __restrict__ bnm, const float* __restrict__ bnv,
    float* __restrict__ y)
{
    __shared__ float s_in[33*33];
    __shared__ float s_w[OC_PB*9];
    const int NOCG = CMID / OC_PB;
    int bz  = blockIdx.z;
    int b   = bz / NOCG, ocg = bz % NOCG;
    int oc0 = ocg * OC_PB;
    int ho0 = blockIdx.y * 16, wo0 = blockIdx.x * 16;
    int ih0 = 2*ho0 - 1, iw0 = 2*wo0 - 1;
    int tid = threadIdx.x;
    int ty  = tid >> 3, tx = tid & 7;

    int  goff[18]; bool gok[18]; bool wok[18];
    #pragma unroll
    for (int it = 0; it < 18; ++it) {
        int idx = tid + it*64;
        int r = idx / 33, c = idx - r*33;
        int ih = ih0 + r, iw = iw0 + c;
        wok[it] = idx < 1089;
        gok[it] = wok[it] && ih >= 0 && ih < H_IN && iw >= 0 && iw < W_IN;
        goff[it] = ih * W_IN + iw;
    }

    float acc[OC_PB][2][2];
    #pragma unroll
    for (int o = 0; o < OC_PB; ++o)
        #pragma unroll
        for (int a = 0; a < 2; ++a)
            #pragma unroll
            for (int d = 0; d < 2; ++d) acc[o][a][d] = 0.f;

    const float* xb = x + (long)b * CIN * H_IN * W_IN;
    for (int ic = 0; ic < CIN; ++ic) {
        const float* xc = xb + (long)ic * H_IN * W_IN;
        #pragma unroll
        for (int it = 0; it < 18; ++it) {
            int idx = tid + it*64;
            if (wok[it]) s_in[idx] = gok[it] ? __ldg(xc + goff[it]) : 0.f;
        }
        for (int i = tid; i < OC_PB*9; i += 64) {
            int oc = i / 9, j = i - oc*9;
            s_w[i] = w[((oc0 + oc)*CIN + ic)*9 + j];
        }
        __syncthreads();

        float v[5][5];
        #pragma unroll
        for (int r = 0; r < 5; ++r)
            #pragma unroll
            for (int c = 0; c < 5; ++c)
                v[r][c] = s_in[(4*ty + r)*33 + 4*tx + c];

        #pragma unroll
        for (int o = 0; o < OC_PB; ++o) {
            #pragma unroll
            for (int ki = 0; ki < 3; ++ki)
                #pragma unroll
                for (int kj = 0; kj < 3; ++kj) {
                    float wv = s_w[o*9 + ki*3 + kj];
                    acc[o][0][0] += wv * v[ki  ][kj  ];
                    acc[o][0][1] += wv * v[ki  ][kj+2];
                    acc[o][1][0] += wv * v[ki+2][kj  ];
                    acc[o][1][1] += wv * v[ki+2][kj+2];
                }
        }
        __syncthreads();
    }

    #pragma unroll
    for (int o = 0; o < OC_PB; ++o) {
        int oc = oc0 + o;
        float s    = bng[oc] * rsqrtf(bnv[oc] + EPSV);
        float bias = bnb[oc] - bnm[oc] * s;
        #pragma unroll
        for (int dy = 0; dy < 2; ++dy)
            #pragma unroll
            for (int dx = 0; dx < 2; ++dx) {
                int ho = ho0 + 2*ty + dy, wo = wo0 + 2*tx + dx;
                float vv = acc[o][dy][dx] * s + bias;
                vv = vv >= 0.f ? vv : 0.1f * vv;
                y[(long)(b*CMID + oc)*NPIX + ho*WO + wo] = vv;
            }
    }
}

// ------------------- 1x1 conv + softmax over 9 (scalar, cat path) ------------
template<int CMID, int G, int CK>
__global__ __launch_bounds__(G*8) void mask_softmax(
    const float* __restrict__ y1, const float* __restrict__ w2,
    float* __restrict__ mask)
{
    const int NT = G*8;
    __shared__ float s_y[CMID*32];
    __shared__ float s_w[G*9*(CK+1)];
    int b  = blockIdx.y;
    int p0 = blockIdx.x * 32;
    int tid = threadIdx.x;
    int g = tid >> 3, q = tid & 7;

    for (int i = tid; i < CMID*32; i += NT) {
        int k = i >> 5, p = i & 31;
        s_y[i] = y1[(long)(b*CMID + k)*NPIX + p0 + p];
    }

    float acc[9][4];
    #pragma unroll
    for (int j = 0; j < 9; ++j)
        #pragma unroll
        for (int i = 0; i < 4; ++i) acc[j][i] = 0.f;

    for (int c0 = 0; c0 < CMID; c0 += CK) {
        __syncthreads();
        for (int i = tid; i < G*9*CK; i += NT) {
            int oc = i / CK, kk = i - oc*CK;
            s_w[oc*(CK+1) + kk] = w2[oc*CMID + c0 + kk];
        }
        __syncthreads();
        #pragma unroll 4
        for (int kk = 0; kk < CK; ++kk) {
            float yv[4];
            #pragma unroll
            for (int i = 0; i < 4; ++i) yv[i] = s_y[(c0 + kk)*32 + q + 8*i];
            #pragma unroll
            for (int j = 0; j < 9; ++j) {
                float wv = s_w[(g*9 + j)*(CK+1) + kk];
                #pragma unroll
                for (int i = 0; i < 4; ++i) acc[j][i] += wv * yv[i];
            }
        }
    }

    #pragma unroll
    for (int i = 0; i < 4; ++i) {
        float m = acc[0][i];
        #pragma unroll
        for (int j = 1; j < 9; ++j) m = fmaxf(m, acc[j][i]);
        float e[9], sum = 0.f;
        #pragma unroll
        for (int j = 0; j < 9; ++j) { e[j] = __expf(acc[j][i] - m); sum += e[j]; }
        float rs = 1.f / sum;
        #pragma unroll
        for (int j = 0; j < 9; ++j)
            mask[(long)(b*G*9 + g*9 + j)*NPIX + p0 + q + 8*i] = e[j] * rs;
    }
}

// ------------------- unfold-weighted-sum aggregation -------------------------
template<int C, int GROUPS>
__global__ __launch_bounds__(256) void aggregate(
    const float* __restrict__ x, const float* __restrict__ mask,
    float* __restrict__ out)
{
    int idx = blockIdx.x * blockDim.x + threadIdx.x;
    if (idx >= BATCH*C*NPIX) return;
    int wo = idx % WO;
    int t  = idx / WO;
    int ho = t % HO; t /= HO;
    int c  = t % C;
    int b  = t / C;
    int g  = c % GROUPS;

    const float* xb = x + (long)(b*C + c) * H_IN * W_IN;
    const float* mb = mask + (long)(b*GROUPS*9 + g*9) * NPIX + ho*WO + wo;

    float acc = 0.f;
    #pragma unroll
    for (int ki = 0; ki < 3; ++ki) {
        int ih = 2*ho - 1 + ki;
        bool okh = (ih >= 0) && (ih < H_IN);
        #pragma unroll
        for (int kj = 0; kj < 3; ++kj) {
            int iw = 2*wo - 1 + kj;
            float xv = (okh && iw >= 0 && iw < W_IN) ? __ldg(xb + ih*W_IN + iw) : 0.f;
            acc += __ldg(mb + (ki*3 + kj)*NPIX) * xv;
        }
    }
    out[idx] = acc;
}

// ------------------- group-wise correlation volume ---------------------------
__global__ __launch_bounds__(128) void vol_gwc(const float* __restrict__ g8,
                                               float* __restrict__ out)
{
    int idx = blockIdx.x * blockDim.x + threadIdx.x;
    int w  = idx % WO;
    int t  = idx / WO;
    int h  = t % HO; t /= HO;
    int g  = t % 8;
    int b2 = t / 8;

    const float* lp = g8 + (long)(b2*96 + g*12) * NPIX + h*WO + w;
    const float* rp = g8 + (long)((b2+2)*96 + g*12) * NPIX + h*WO;
    float lv[12];
    #pragma unroll
    for (int c = 0; c < 12; ++c) lv[c] = lp[c*NPIX];

    float* ob = out + (long)(b2*32 + g) * DISP * NPIX + h*WO + w;
    for (int d = 0; d < DISP; ++d) {
        float val = 0.f;
        if (d <= w) {
            float s = 0.f;
            #pragma unroll
            for (int c = 0; c < 12; ++c) s += lv[c] * __ldg(rp + c*NPIX + (w - d));
            val = s * (1.f/12.f);
        }
        ob[(long)d*NPIX] = val;
    }
}

// ------------------- concat volume -------------------------------------------
__global__ __launch_bounds__(256) void vol_cat(const float* __restrict__ c8,
                                               float* __restrict__ out)
{
    int idx = blockIdx.x * blockDim.x + threadIdx.x;
    int w  = idx % WO;
    int t  = idx / WO;
    int h  = t % HO; t /= HO;
    int d  = t % DISP; t /= DISP;
    int ch = t % 24;
    int b2 = t / 24;

    float val = 0.f;
    if (w >= d) {
        if (ch < 12)
            val = __ldg(c8 + (long)(b2*12 + ch) * NPIX + h*WO + w);
        else
            val = __ldg(c8 + (long)((b2+2)*12 + (ch-12)) * NPIX + h*WO + (w - d));
    }
    out[(long)(b2*32 + 8 + ch) * DISP * NPIX + (long)d*NPIX + h*WO + w] = val;
}

// ------------------- launch --------------------------------------------------
extern "C" void kernel_launch(void* const* d_in, const int* in_sizes, int n_in,
                              void* d_out, int out_size)
{
    const float* gwc_f = (const float*)d_in[0];
    const float* cat_f = (const float*)d_in[1];
    const float* g_w1  = (const float*)d_in[2];
    const float* g_bg  = (const float*)d_in[3];
    const float* g_bb  = (const float*)d_in[4];
    const float* g_bm  = (const float*)d_in[5];
    const float* g_bv  = (const float*)d_in[6];
    const float* g_w2  = (const float*)d_in[7];
    const float* c_w1  = (const float*)d_in[8];
    const float* c_bg  = (const float*)d_in[9];
    const float* c_bb  = (const float*)d_in[10];
    const float* c_bm  = (const float*)d_in[11];
    const float* c_bv  = (const float*)d_in[12];
    const float* c_w2  = (const float*)d_in[13];
    float* out = (float*)d_out;

    float *y1g, *y1c, *mg, *mc, *g8, *c8;
    unsigned *wc1hi, *wc1lo, *w2hi, *w2lo;
    cudaGetSymbolAddress((void**)&y1g, g_y1g);
    cudaGetSymbolAddress((void**)&y1c, g_y1c);
    cudaGetSymbolAddress((void**)&mg,  g_mg);
    cudaGetSymbolAddress((void**)&mc,  g_mc);
    cudaGetSymbolAddress((void**)&g8,  g_g8);
    cudaGetSymbolAddress((void**)&c8,  g_c8);
    cudaGetSymbolAddress((void**)&wc1hi, g_wc1hi);
    cudaGetSymbolAddress((void**)&wc1lo, g_wc1lo);
    cudaGetSymbolAddress((void**)&w2hi,  g_w2hi);
    cudaGetSymbolAddress((void**)&w2lo,  g_w2lo);

    // 0) weight prep (packed bf16 hi/lo in staging layout)
    wprep_conv1<<<(27*192*16 + 255)/256, 256>>>(g_w1, wc1hi, wc1lo);
    wprep_mask <<<(6*144*16 + 255)/256, 256>>>(g_w2, w2hi, w2lo);

    // 1) conv1 + BN + leaky
    cudaFuncSetAttribute(conv1_gwc_mma, cudaFuncAttributeMaxDynamicSharedMemorySize, SMEM_CONV1);
    conv1_gwc_mma<<<360, 256, SMEM_CONV1>>>(gwc_f, wc1hi, wc1lo, g_bg, g_bb, g_bm, g_bv, y1g);
    conv1_bn_lrelu<12, 24, 8><<<dim3(9,5,BATCH*3), 64>>>(cat_f, c_w1, c_bg, c_bb, c_bm, c_bv, y1c);

    // 2) 1x1 conv + softmax masks (gwc path tensorized)
    cudaFuncSetAttribute(mask_mma_gwc, cudaFuncAttributeMaxDynamicSharedMemorySize, SMEM_MASK);
    mask_mma_gwc<<<360, 256, SMEM_MASK>>>(y1g, w2hi, w2lo, mg);
    mask_softmax<24,12,24><<<dim3(360,BATCH), 96>>>(y1c, c_w2, mc);

    // 3) adaptive aggregation
    aggregate<96,16><<<(BATCH*96*NPIX)/256, 256>>>(gwc_f, mg, g8);
    aggregate<12,12><<<(BATCH*12*NPIX)/256, 256>>>(cat_f, mc, c8);

    // 4) cost volumes into output
    vol_gwc<<<(2*8*NPIX)/128, 128>>>(g8, out);
    vol_cat<<<(2*24*DISP*NPIX)/256, 256>>>(c8, out);
}

// round 6
// speedup vs baseline: 2.3921x; 1.0427x over previous
#include <cuda_runtime.h>
#include <cstdint>

#define H_IN 160
#define W_IN 288
#define HO   80
#define WO   144
#define NPIX (HO*WO)          // 11520
#define BATCH 4
#define EPSV 1e-5f
#define DISP 24

// ------------------- scratch (static device memory, no allocs) ---------------
__device__ float g_y1g[BATCH*192*NPIX];
__device__ float g_y1c[BATCH*24*NPIX];
__device__ float g_mg [BATCH*144*NPIX];
__device__ float g_mc [BATCH*108*NPIX];
__device__ float g_g8 [BATCH*96*NPIX];
__device__ float g_c8 [BATCH*12*NPIX];
__device__ unsigned g_wc1hi[27*192*16];
__device__ unsigned g_wc1lo[27*192*16];
__device__ unsigned g_w2hi [6*144*16];
__device__ unsigned g_w2lo [6*144*16];

// ===================== small helpers ========================================
__device__ __forceinline__ unsigned smem_u32(const void* p){
    unsigned a;
    asm("{ .reg .u64 t; cvta.to.shared.u64 t, %1; cvt.u32.u64 %0, t; }"
        : "=r"(a) : "l"(p));
    return a;
}
__device__ __forceinline__ unsigned short bf16hi(float x){
    unsigned u = __float_as_uint(x);
    unsigned r = u + 0x7fffu + ((u >> 16) & 1u);
    return (unsigned short)(r >> 16);
}
__device__ __forceinline__ float bf16f(unsigned short h){
    return __uint_as_float(((unsigned)h) << 16);
}
__device__ __forceinline__ unsigned pack2(unsigned short a, unsigned short b){
    return (unsigned)a | ((unsigned)b << 16);
}
__device__ __forceinline__ void ldm4(unsigned* r, unsigned addr){
    asm volatile("ldmatrix.sync.aligned.m8n8.x4.shared.b16 {%0,%1,%2,%3}, [%4];"
        : "=r"(r[0]), "=r"(r[1]), "=r"(r[2]), "=r"(r[3]) : "r"(addr));
}
__device__ __forceinline__ void mma_bf16(float* c, const unsigned* a,
                                         unsigned b0, unsigned b1){
    asm volatile("mma.sync.aligned.m16n8k16.row.col.f32.bf16.bf16.f32 "
        "{%0,%1,%2,%3}, {%4,%5,%6,%7}, {%8,%9}, {%0,%1,%2,%3};"
        : "+f"(c[0]), "+f"(c[1]), "+f"(c[2]), "+f"(c[3])
        : "r"(a[0]), "r"(a[1]), "r"(a[2]), "r"(a[3]), "r"(b0), "r"(b1));
}

// ===================== weight prep (packed bf16 hi/lo, staging layout) =======
__global__ __launch_bounds__(256) void wprep_conv1(const float* __restrict__ w,
                                                   unsigned* __restrict__ whi,
                                                   unsigned* __restrict__ wlo)
{
    int idx = blockIdx.x * 256 + threadIdx.x;
    if (idx >= 27*192*16) return;
    int kk = idx & 15;
    int row = (idx >> 4) % 192;
    int c   = idx / (192*16);
    int k0 = c*32 + 2*kk, k1 = k0 + 1;
    int tap0 = k0 / 96, ic0 = k0 - tap0*96;
    int tap1 = k1 / 96, ic1 = k1 - tap1*96;
    float v0 = w[row*864 + ic0*9 + tap0];
    float v1 = w[row*864 + ic1*9 + tap1];
    unsigned short h0 = bf16hi(v0), h1 = bf16hi(v1);
    whi[idx] = pack2(h0, h1);
    wlo[idx] = pack2(bf16hi(v0 - bf16f(h0)), bf16hi(v1 - bf16f(h1)));
}

__global__ __launch_bounds__(256) void wprep_mask(const float* __restrict__ w2,
                                                  unsigned* __restrict__ whi,
                                                  unsigned* __restrict__ wlo)
{
    int idx = blockIdx.x * 256 + threadIdx.x;
    if (idx >= 6*144*16) return;
    int kk = idx & 15;
    int row = (idx >> 4) % 144;
    int c   = idx / (144*16);
    int k0 = c*32 + 2*kk;
    float v0 = w2[row*192 + k0];
    float v1 = w2[row*192 + k0 + 1];
    unsigned short h0 = bf16hi(v0), h1 = bf16hi(v1);
    whi[idx] = pack2(h0, h1);
    wlo[idx] = pack2(bf16hi(v0 - bf16f(h0)), bf16hi(v1 - bf16f(h1)));
}

// ===================== conv1 gwc: implicit GEMM on mma.sync bf16 =============
#define C1_A_HI 1536
#define C1_A_LO (C1_A_HI + 10240)
#define C1_B_HI (C1_A_LO + 10240)
#define C1_B_LO (C1_B_HI + 15360)
#define SMEM_CONV1 (C1_B_LO + 15360)

__global__ __launch_bounds__(256, 1) void conv1_gwc_mma(
    const float* __restrict__ x,
    const unsigned* __restrict__ whi, const unsigned* __restrict__ wlo,
    const float* __restrict__ bng, const float* __restrict__ bnb,
    const float* __restrict__ bnm, const float* __restrict__ bnv,
    float* __restrict__ y)
{
    extern __shared__ char smem[];
    const unsigned sb = smem_u32(smem);
    const int tid = threadIdx.x;
    const int wid = tid >> 5, lane = tid & 31;
    float* sbn = (float*)smem;

    if (tid < 192) {
        float s = bng[tid] * rsqrtf(bnv[tid] + EPSV);
        sbn[tid] = s;
        sbn[192 + tid] = bnb[tid] - bnm[tid] * s;
    }

    const int m = tid & 127;
    const int khalf = tid >> 7;
    const int p  = blockIdx.x*128 + m;
    const int b  = p / NPIX;
    const int r  = p - b*NPIX;
    const int ho = r / WO, wo = r - (r/WO)*WO;
    const float* xb = x + (size_t)b * 96 * H_IN * W_IN;

    const int brow4 = tid >> 2, bq4 = (tid & 3)*4;

    const int wm = wid & 1, wn = wid >> 1;
    const unsigned aHiB = sb + C1_A_HI + ((wm*64 + (lane&15))*40 + (lane>>4)*8)*2;
    const unsigned aLoB = aHiB + 10240;
    const unsigned bHiB = sb + C1_B_HI + ((wn*48 + (lane&15))*40 + (lane>>4)*8)*2;
    const unsigned bLoB = bHiB + 15360;

    unsigned* sAhi = (unsigned*)(smem + C1_A_HI);
    unsigned* sAlo = (unsigned*)(smem + C1_A_LO);

    float acc[4][6][4];
    #pragma unroll
    for (int f = 0; f < 4; ++f)
        #pragma unroll
        for (int g = 0; g < 6; ++g)
            #pragma unroll
            for (int i = 0; i < 4; ++i) acc[f][g][i] = 0.f;

    float av[16];
    uint4 bhv[3], blv[3];

    {
        int ih = 2*ho - 1, iw = 2*wo - 1;
        bool ok = (ih >= 0) && (iw >= 0);
        const float* ptr = xb + ((size_t)(khalf*16)*H_IN + ih)*W_IN + iw;
        #pragma unroll
        for (int j = 0; j < 16; ++j)
            av[j] = ok ? __ldg(ptr + (size_t)j*H_IN*W_IN) : 0.f;
        #pragma unroll
        for (int it = 0; it < 3; ++it) {
            int e = (brow4 + it*64)*16 + bq4;
            bhv[it] = __ldg((const uint4*)(whi + e));
            blv[it] = __ldg((const uint4*)(wlo + e));
        }
    }

    for (int c = 0; c < 27; ++c) {
        {
            int wbase = m*20 + khalf*8;
            #pragma unroll
            for (int jj = 0; jj < 8; ++jj) {
                float v0 = av[2*jj], v1 = av[2*jj+1];
                unsigned short h0 = bf16hi(v0), h1 = bf16hi(v1);
                unsigned short l0 = bf16hi(v0 - bf16f(h0));
                unsigned short l1 = bf16hi(v1 - bf16f(h1));
                sAhi[wbase + jj] = pack2(h0, h1);
                sAlo[wbase + jj] = pack2(l0, l1);
            }
            #pragma unroll
            for (int it = 0; it < 3; ++it) {
                int so = ((brow4 + it*64)*20 + bq4)*4;
                *(uint4*)(smem + C1_B_HI + so) = bhv[it];
                *(uint4*)(smem + C1_B_LO + so) = blv[it];
            }
        }
        __syncthreads();

        if (c < 26) {
            int cn = c + 1;
            int tap = cn / 3;
            int ic0 = (cn - tap*3)*32 + khalf*16;
            int ki = tap / 3, kj = tap - ki*3;
            int ih = 2*ho - 1 + ki, iw = 2*wo - 1 + kj;
            bool ok = (ih >= 0) && (iw >= 0);
            const float* ptr = xb + ((size_t)ic0*H_IN + ih)*W_IN + iw;
            #pragma unroll
            for (int j = 0; j < 16; ++j)
                av[j] = ok ? __ldg(ptr + (size_t)j*H_IN*W_IN) : 0.f;
            #pragma unroll
            for (int it = 0; it < 3; ++it) {
                int e = (cn*192 + brow4 + it*64)*16 + bq4;
                bhv[it] = __ldg((const uint4*)(whi + e));
                blv[it] = __ldg((const uint4*)(wlo + e));
            }
        }

        #pragma unroll
        for (int kst = 0; kst < 2; ++kst) {
            unsigned ko = kst*32;
            unsigned ah[4][4], al[4][4];
            #pragma unroll
            for (int f = 0; f < 4; ++f) {
                ldm4(ah[f], aHiB + f*1280 + ko);
                ldm4(al[f], aLoB + f*1280 + ko);
            }
            #pragma unroll
            for (int g2 = 0; g2 < 3; ++g2) {
                unsigned bh[4], bl[4];
                ldm4(bh, bHiB + g2*1280 + ko);
                ldm4(bl, bLoB + g2*1280 + ko);
                #pragma unroll
                for (int f = 0; f < 4; ++f) {
                    mma_bf16(acc[f][2*g2],   ah[f], bh[0], bh[2]);
                    mma_bf16(acc[f][2*g2+1], ah[f], bh[1], bh[3]);
                    mma_bf16(acc[f][2*g2],   ah[f], bl[0], bl[2]);
                    mma_bf16(acc[f][2*g2+1], ah[f], bl[1], bl[3]);
                    mma_bf16(acc[f][2*g2],   al[f], bh[0], bh[2]);
                    mma_bf16(acc[f][2*g2+1], al[f], bh[1], bh[3]);
                }
            }
        }
        __syncthreads();
    }

    float* sEpi = (float*)(smem + C1_A_HI);
    #pragma unroll
    for (int half = 0; half < 2; ++half) {
        if (wm == half) {
            #pragma unroll
            for (int f = 0; f < 4; ++f) {
                int row0 = f*16 + (lane >> 2);
                #pragma unroll
                for (int g = 0; g < 6; ++g) {
                    int col0 = wn*48 + g*8 + 2*(lane & 3);
                    float s0 = sbn[col0],     b0v = sbn[192 + col0];
                    float s1 = sbn[col0 + 1], b1v = sbn[192 + col0 + 1];
                    float v;
                    v = acc[f][g][0]*s0 + b0v; v = v >= 0.f ? v : 0.1f*v; sEpi[ row0   *193 + col0  ] = v;
                    v = acc[f][g][1]*s1 + b1v; v = v >= 0.f ? v : 0.1f*v; sEpi[ row0   *193 + col0+1] = v;
                    v = acc[f][g][2]*s0 + b0v; v = v >= 0.f ? v : 0.1f*v; sEpi[(row0+8)*193 + col0  ] = v;
                    v = acc[f][g][3]*s1 + b1v; v = v >= 0.f ? v : 0.1f*v; sEpi[(row0+8)*193 + col0+1] = v;
                }
            }
        }
        __syncthreads();
        int p0 = blockIdx.x*128 + half*64;
        int bb = p0 / NPIX;
        int rb = p0 - bb*NPIX;
        #pragma unroll 4
        for (int i = 0; i < 48; ++i) {
            int idx = tid + i*256;
            int mm = idx & 63, oc = idx >> 6;
            y[((size_t)bb*192 + oc)*NPIX + rb + mm] = sEpi[mm*193 + oc];
        }
        __syncthreads();
    }
}

// ===================== gwc mask: MMA conv 1x1 + fused softmax ================
#define MKA_HI 0
#define MKA_LO 10240
#define MKB_HI 20480
#define MKB_LO 32000
#define SMEM_MASK (128*145*4)

__global__ __launch_bounds__(256, 1) void mask_mma_gwc(
    const float* __restrict__ y1,
    const unsigned* __restrict__ whi, const unsigned* __restrict__ wlo,
    float* __restrict__ mask)
{
    extern __shared__ char smem[];
    const unsigned sb = smem_u32(smem);
    const int tid = threadIdx.x;
    const int wid = tid >> 5, lane = tid & 31;
    const int p0 = blockIdx.x * 128;
    const int b  = p0 / NPIX;
    const int pp = p0 - b*NPIX;
    const float* yb = y1 + (size_t)b*192*NPIX + pp;

    unsigned* sAhi = (unsigned*)(smem + MKA_HI);
    unsigned* sAlo = (unsigned*)(smem + MKA_LO);

    const int am  = tid & 127, ahb = tid >> 7;
    const int brow4 = tid >> 2, bq4 = (tid & 3)*4;

    const unsigned aB = sb + MKA_HI + ((wid*16 + (lane&15))*40 + (lane>>4)*8)*2;
    const unsigned bB = sb + MKB_HI + (((lane&15))*40 + (lane>>4)*8)*2;

    float acc[18][4];
    #pragma unroll
    for (int j = 0; j < 18; ++j)
        #pragma unroll
        for (int i = 0; i < 4; ++i) acc[j][i] = 0.f;

    float av[16];
    uint4 bhv[3], blv[3];

    #pragma unroll
    for (int i = 0; i < 8; ++i) {
        int q = ahb + 2*i;
        av[2*i]   = __ldg(yb + (size_t)(2*q)  *NPIX + am);
        av[2*i+1] = __ldg(yb + (size_t)(2*q+1)*NPIX + am);
    }
    #pragma unroll
    for (int it = 0; it < 3; ++it) {
        int row = brow4 + it*64;
        if (row < 144) {
            int e = row*16 + bq4;
            bhv[it] = __ldg((const uint4*)(whi + e));
            blv[it] = __ldg((const uint4*)(wlo + e));
        }
    }

    for (int c = 0; c < 6; ++c) {
        #pragma unroll
        for (int i = 0; i < 8; ++i) {
            int q = ahb + 2*i;
            float v0 = av[2*i], v1 = av[2*i+1];
            unsigned short h0 = bf16hi(v0), h1 = bf16hi(v1);
            unsigned short l0 = bf16hi(v0 - bf16f(h0));
            unsigned short l1 = bf16hi(v1 - bf16f(h1));
            sAhi[am*20 + q] = pack2(h0, h1);
            sAlo[am*20 + q] = pack2(l0, l1);
        }
        #pragma unroll
        for (int it = 0; it < 3; ++it) {
            int row = brow4 + it*64;
            if (row < 144) {
                int so = (row*20 + bq4)*4;
                *(uint4*)(smem + MKB_HI + so) = bhv[it];
                *(uint4*)(smem + MKB_LO + so) = blv[it];
            }
        }
        __syncthreads();

        if (c < 5) {
            int kb = (c + 1) * 32;
            #pragma unroll
            for (int i = 0; i < 8; ++i) {
                int q = ahb + 2*i;
                av[2*i]   = __ldg(yb + (size_t)(kb + 2*q)  *NPIX + am);
                av[2*i+1] = __ldg(yb + (size_t)(kb + 2*q+1)*NPIX + am);
            }
            #pragma unroll
            for (int it = 0; it < 3; ++it) {
                int row = brow4 + it*64;
                if (row < 144) {
                    int e = ((c+1)*144 + row)*16 + bq4;
                    bhv[it] = __ldg((const uint4*)(whi + e));
                    blv[it] = __ldg((const uint4*)(wlo + e));
                }
            }
        }

        #pragma unroll
        for (int ks = 0; ks < 2; ++ks) {
            unsigned ko = ks*32;
            unsigned ah[4], al[4];
            ldm4(ah, aB + ko);
            ldm4(al, aB + (MKA_LO - MKA_HI) + ko);
            #pragma unroll
            for (int jp = 0; jp < 9; ++jp) {
                unsigned bh[4], bl[4];
                ldm4(bh, bB + jp*1280 + ko);
                ldm4(bl, bB + (MKB_LO - MKB_HI) + jp*1280 + ko);
                mma_bf16(acc[2*jp],   ah, bh[0], bh[2]);
                mma_bf16(acc[2*jp+1], ah, bh[1], bh[3]);
                mma_bf16(acc[2*jp],   ah, bl[0], bl[2]);
                mma_bf16(acc[2*jp+1], ah, bl[1], bl[3]);
                mma_bf16(acc[2*jp],   al, bh[0], bh[2]);
                mma_bf16(acc[2*jp+1], al, bh[1], bh[3]);
            }
        }
        __syncthreads();
    }

    float* sC = (float*)smem;
    {
        int r0 = wid*16 + (lane >> 2);
        #pragma unroll
        for (int j = 0; j < 18; ++j) {
            int c0 = j*8 + 2*(lane & 3);
            sC[ r0   *145 + c0  ] = acc[j][0];
            sC[ r0   *145 + c0+1] = acc[j][1];
            sC[(r0+8)*145 + c0  ] = acc[j][2];
            sC[(r0+8)*145 + c0+1] = acc[j][3];
        }
    }
    __syncthreads();

    const int sm = tid & 127;
    const float* srow = sC + sm*145;
    #pragma unroll
    for (int gi = 0; gi < 8; ++gi) {
        int g = (tid >> 7)*8 + gi;
        float v[9];
        #pragma unroll
        for (int j = 0; j < 9; ++j) v[j] = srow[g*9 + j];
        float mx = v[0];
        #pragma unroll
        for (int j = 1; j < 9; ++j) mx = fmaxf(mx, v[j]);
        float e[9], sum = 0.f;
        #pragma unroll
        for (int j = 0; j < 9; ++j) { e[j] = __expf(v[j] - mx); sum += e[j]; }
        float rs = 1.f / sum;
        float* mrow = mask + ((size_t)b*144 + g*9)*NPIX + pp + sm;
        #pragma unroll
        for (int j = 0; j < 9; ++j) mrow[(size_t)j*NPIX] = e[j]*rs;
    }
}

// ------------------- cat conv1: 3x3 s2 + BN + leaky, 256-thread tiles --------
__global__ __launch_bounds__(256) void conv1_cat(
    const float* __restrict__ x, const float* __restrict__ w,
    const float* __restrict__ bng, const float* __restrict__ bnb,
    const float* __restrict__ bnm, const float* __restrict__ bnv,
    float* __restrict__ y)
{
    __shared__ float s_in[33*33];
    __shared__ float s_w[24*9];
    const int b   = blockIdx.z;
    const int ho0 = blockIdx.y * 16, wo0 = blockIdx.x * 16;
    const int tid = threadIdx.x;
    const int ty = tid >> 4, tx = tid & 15;
    const int ih0 = 2*ho0 - 1, iw0 = 2*wo0 - 1;

    float acc[24];
    #pragma unroll
    for (int o = 0; o < 24; ++o) acc[o] = 0.f;

    const float* xb = x + (size_t)b * 12 * H_IN * W_IN;
    for (int ic = 0; ic < 12; ++ic) {
        const float* xc = xb + (size_t)ic * H_IN * W_IN;
        #pragma unroll
        for (int it = 0; it < 5; ++it) {
            int i = tid + it*256;
            if (i < 1089) {
                int rr = i / 33, cc = i - rr*33;
                int ih = ih0 + rr, iw = iw0 + cc;
                s_in[i] = (ih >= 0 && ih < H_IN && iw >= 0 && iw < W_IN)
                          ? __ldg(xc + ih*W_IN + iw) : 0.f;
            }
        }
        if (tid < 216) {
            int oc = tid / 9, tap = tid - oc*9;
            s_w[tid] = w[(oc*12 + ic)*9 + tap];
        }
        __syncthreads();

        float v[3][3];
        #pragma unroll
        for (int ki = 0; ki < 3; ++ki)
            #pragma unroll
            for (int kj = 0; kj < 3; ++kj)
                v[ki][kj] = s_in[(2*ty + ki)*33 + 2*tx + kj];

        #pragma unroll
        for (int o = 0; o < 24; ++o) {
            float a = acc[o];
            #pragma unroll
            for (int ki = 0; ki < 3; ++ki)
                #pragma unroll
                for (int kj = 0; kj < 3; ++kj)
                    a += s_w[o*9 + ki*3 + kj] * v[ki][kj];
            acc[o] = a;
        }
        __syncthreads();
    }

    const int ho = ho0 + ty, wo = wo0 + tx;
    #pragma unroll
    for (int o = 0; o < 24; ++o) {
        float s    = __ldg(bng + o) * rsqrtf(__ldg(bnv + o) + EPSV);
        float bias = __ldg(bnb + o) - __ldg(bnm + o) * s;
        float vv = acc[o] * s + bias;
        vv = vv >= 0.f ? vv : 0.1f * vv;
        y[((size_t)b*24 + o)*NPIX + ho*WO + wo] = vv;
    }
}

// ------------------- 1x1 conv + softmax over 9 (scalar, cat path) ------------
template<int CMID, int G, int CK>
__global__ __launch_bounds__(G*8) void mask_softmax(
    const float* __restrict__ y1, const float* __restrict__ w2,
    float* __restrict__ mask)
{
    const int NT = G*8;
    __shared__ float s_y[CMID*32];
    __shared__ float s_w[G*9*(CK+1)];
    int b  = blockIdx.y;
    int p0 = blockIdx.x * 32;
    int tid = threadIdx.x;
    int g = tid >> 3, q = tid & 7;

    for (int i = tid; i < CMID*32; i += NT) {
        int k = i >> 5, p = i & 31;
        s_y[i] = y1[(long)(b*CMID + k)*NPIX + p0 + p];
    }

    float acc[9][4];
    #pragma unroll
    for (int j = 0; j < 9; ++j)
        #pragma unroll
        for (int i = 0; i < 4; ++i) acc[j][i] = 0.f;

    for (int c0 = 0; c0 < CMID; c0 += CK) {
        __syncthreads();
        for (int i = tid; i < G*9*CK; i += NT) {
            int oc = i / CK, kk = i - oc*CK;
            s_w[oc*(CK+1) + kk] = w2[oc*CMID + c0 + kk];
        }
        __syncthreads();
        #pragma unroll 4
        for (int kk = 0; kk < CK; ++kk) {
            float yv[4];
            #pragma unroll
            for (int i = 0; i < 4; ++i) yv[i] = s_y[(c0 + kk)*32 + q + 8*i];
            #pragma unroll
            for (int j = 0; j < 9; ++j) {
                float wv = s_w[(g*9 + j)*(CK+1) + kk];
                #pragma unroll
                for (int i = 0; i < 4; ++i) acc[j][i] += wv * yv[i];
            }
        }
    }

    #pragma unroll
    for (int i = 0; i < 4; ++i) {
        float m = acc[0][i];
        #pragma unroll
        for (int j = 1; j < 9; ++j) m = fmaxf(m, acc[j][i]);
        float e[9], sum = 0.f;
        #pragma unroll
        for (int j = 0; j < 9; ++j) { e[j] = __expf(acc[j][i] - m); sum += e[j]; }
        float rs = 1.f / sum;
        #pragma unroll
        for (int j = 0; j < 9; ++j)
            mask[(long)(b*G*9 + g*9 + j)*NPIX + p0 + q + 8*i] = e[j] * rs;
    }
}

// ------------------- gwc aggregation: 6 channels per thread ------------------
__global__ __launch_bounds__(256) void aggregate_gwc(
    const float* __restrict__ x, const float* __restrict__ mask,
    float* __restrict__ out)
{
    int idx = blockIdx.x * 256 + threadIdx.x;   // BATCH*16*NPIX
    int wo = idx % WO;
    int t  = idx / WO;
    int ho = t % HO; t /= HO;
    int g  = t % 16;
    int b  = t / 16;

    const float* mb = mask + ((size_t)b*144 + g*9) * NPIX + ho*WO + wo;
    float mreg[9];
    #pragma unroll
    for (int j = 0; j < 9; ++j) mreg[j] = __ldg(mb + (size_t)j*NPIX);

    const float* xg = x + ((size_t)b*96 + g) * H_IN * W_IN;
    float* og = out + ((size_t)b*96 + g) * NPIX + ho*WO + wo;

    #pragma unroll
    for (int cc = 0; cc < 6; ++cc) {
        const float* xc = xg + (size_t)cc*16*H_IN*W_IN;
        float acc = 0.f;
        #pragma unroll
        for (int ki = 0; ki < 3; ++ki) {
            int ih = 2*ho - 1 + ki;
            bool okh = (ih >= 0) && (ih < H_IN);
            #pragma unroll
            for (int kj = 0; kj < 3; ++kj) {
                int iw = 2*wo - 1 + kj;
                float xv = (okh && iw >= 0 && iw < W_IN) ? __ldg(xc + ih*W_IN + iw) : 0.f;
                acc += mreg[ki*3 + kj] * xv;
            }
        }
        og[(size_t)cc*16*NPIX] = acc;
    }
}

// ------------------- cat aggregation (1 ch per group) ------------------------
__global__ __launch_bounds__(256) void aggregate_cat(
    const float* __restrict__ x, const float* __restrict__ mask,
    float* __restrict__ out)
{
    int idx = blockIdx.x * 256 + threadIdx.x;   // BATCH*12*NPIX
    int wo = idx % WO;
    int t  = idx / WO;
    int ho = t % HO; t /= HO;
    int c  = t % 12;
    int b  = t / 12;

    const float* xb = x + ((size_t)b*12 + c) * H_IN * W_IN;
    const float* mb = mask + ((size_t)b*108 + c*9) * NPIX + ho*WO + wo;

    float acc = 0.f;
    #pragma unroll
    for (int ki = 0; ki < 3; ++ki) {
        int ih = 2*ho - 1 + ki;
        bool okh = (ih >= 0) && (ih < H_IN);
        #pragma unroll
        for (int kj = 0; kj < 3; ++kj) {
            int iw = 2*wo - 1 + kj;
            float xv = (okh && iw >= 0 && iw < W_IN) ? __ldg(xb + ih*W_IN + iw) : 0.f;
            acc += __ldg(mb + (ki*3 + kj)*NPIX) * xv;
        }
    }
    out[idx] = acc;
}

// ------------------- group-wise correlation volume (smem row cache) ----------
__global__ __launch_bounds__(144) void vol_gwc(const float* __restrict__ g8,
                                               float* __restrict__ out)
{
    __shared__ float sr[12][WO];
    const int w  = threadIdx.x;
    int t = blockIdx.x;                  // 2*8*HO
    const int h  = t % HO; t /= HO;
    const int g  = t % 8;
    const int b2 = t / 8;

    const float* lp = g8 + ((size_t)(b2*96 + g*12)) * NPIX + h*WO;
    const float* rp = g8 + ((size_t)((b2+2)*96 + g*12)) * NPIX + h*WO;
    float lv[12];
    #pragma unroll
    for (int c = 0; c < 12; ++c) {
        lv[c] = lp[(size_t)c*NPIX + w];
        sr[c][w] = rp[(size_t)c*NPIX + w];
    }
    __syncthreads();

    float* ob = out + ((size_t)(b2*32 + g)) * DISP * NPIX + h*WO + w;
    #pragma unroll 4
    for (int d = 0; d < DISP; ++d) {
        float val = 0.f;
        if (d <= w) {
            float s = 0.f;
            #pragma unroll
            for (int c = 0; c < 12; ++c) s += lv[c] * sr[c][w - d];
            val = s * (1.f/12.f);
        }
        ob[(size_t)d*NPIX] = val;
    }
}

// ------------------- concat volume (float4 stores) ---------------------------
__global__ __launch_bounds__(256) void vol_cat(const float* __restrict__ c8,
                                               float* __restrict__ out)
{
    int idx = blockIdx.x * 256 + threadIdx.x;   // 2*24*DISP*NPIX/4
    int w4 = (idx % 36) * 4;
    int t  = idx / 36;
    int h  = t % HO; t /= HO;
    int d  = t % DISP; t /= DISP;
    int ch = t % 24;
    int b2 = t / 24;

    float4 val = make_float4(0.f, 0.f, 0.f, 0.f);
    float* vp = &val.x;
    if (ch < 12) {
        const float* base = c8 + ((size_t)(b2*12 + ch)) * NPIX + h*WO;
        #pragma unroll
        for (int j = 0; j < 4; ++j) {
            int w = w4 + j;
            if (w >= d) vp[j] = __ldg(base + w);
        }
    } else {
        const float* base = c8 + ((size_t)((b2+2)*12 + (ch-12))) * NPIX + h*WO;
        #pragma unroll
        for (int j = 0; j < 4; ++j) {
            int w = w4 + j;
            if (w >= d) vp[j] = __ldg(base + w - d);
        }
    }
    *(float4*)(out + ((size_t)(b2*32 + 8 + ch)) * DISP * NPIX
                   + (size_t)d*NPIX + h*WO + w4) = val;
}

// ------------------- launch --------------------------------------------------
extern "C" void kernel_launch(void* const* d_in, const int* in_sizes, int n_in,
                              void* d_out, int out_size)
{
    const float* gwc_f = (const float*)d_in[0];
    const float* cat_f = (const float*)d_in[1];
    const float* g_w1  = (const float*)d_in[2];
    const float* g_bg  = (const float*)d_in[3];
    const float* g_bb  = (const float*)d_in[4];
    const float* g_bm  = (const float*)d_in[5];
    const float* g_bv  = (const float*)d_in[6];
    const float* g_w2  = (const float*)d_in[7];
    const float* c_w1  = (const float*)d_in[8];
    const float* c_bg  = (const float*)d_in[9];
    const float* c_bb  = (const float*)d_in[10];
    const float* c_bm  = (const float*)d_in[11];
    const float* c_bv  = (const float*)d_in[12];
    const float* c_w2  = (const float*)d_in[13];
    float* out = (float*)d_out;

    float *y1g, *y1c, *mg, *mc, *g8, *c8;
    unsigned *wc1hi, *wc1lo, *w2hi, *w2lo;
    cudaGetSymbolAddress((void**)&y1g, g_y1g);
    cudaGetSymbolAddress((void**)&y1c, g_y1c);
    cudaGetSymbolAddress((void**)&mg,  g_mg);
    cudaGetSymbolAddress((void**)&mc,  g_mc);
    cudaGetSymbolAddress((void**)&g8,  g_g8);
    cudaGetSymbolAddress((void**)&c8,  g_c8);
    cudaGetSymbolAddress((void**)&wc1hi, g_wc1hi);
    cudaGetSymbolAddress((void**)&wc1lo, g_wc1lo);
    cudaGetSymbolAddress((void**)&w2hi,  g_w2hi);
    cudaGetSymbolAddress((void**)&w2lo,  g_w2lo);

    // 0) weight prep
    wprep_conv1<<<(27*192*16 + 255)/256, 256>>>(g_w1, wc1hi, wc1lo);
    wprep_mask <<<(6*144*16 + 255)/256, 256>>>(g_w2, w2hi, w2lo);

    // 1) conv1 + BN + leaky
    cudaFuncSetAttribute(conv1_gwc_mma, cudaFuncAttributeMaxDynamicSharedMemorySize, SMEM_CONV1);
    conv1_gwc_mma<<<360, 256, SMEM_CONV1>>>(gwc_f, wc1hi, wc1lo, g_bg, g_bb, g_bm, g_bv, y1g);
    conv1_cat<<<dim3(9,5,BATCH), 256>>>(cat_f, c_w1, c_bg, c_bb, c_bm, c_bv, y1c);

    // 2) 1x1 conv + softmax masks
    cudaFuncSetAttribute(mask_mma_gwc, cudaFuncAttributeMaxDynamicSharedMemorySize, SMEM_MASK);
    mask_mma_gwc<<<360, 256, SMEM_MASK>>>(y1g, w2hi, w2lo, mg);
    mask_softmax<24,12,24><<<dim3(360,BATCH), 96>>>(y1c, c_w2, mc);

    // 3) adaptive aggregation
    aggregate_gwc<<<(BATCH*16*NPIX)/256, 256>>>(gwc_f, mg, g8);
    aggregate_cat<<<(BATCH*12*NPIX)/256, 256>>>(cat_f, mc, c8);

    // 4) cost volumes into output
    vol_gwc<<<2*8*HO, 144>>>(g8, out);
    vol_cat<<<(2*24*DISP*NPIX/4)/256, 256>>>(c8, out);
}

// round 7
// speedup vs baseline: 2.7137x; 1.1344x over previous
#include <cuda_runtime.h>
#include <cstdint>

#define H_IN 160
#define W_IN 288
#define HO   80
#define WO   144
#define NPIX (HO*WO)          // 11520
#define BATCH 4
#define EPSV 1e-5f
#define DISP 24

// ------------------- scratch (static device memory, no allocs) ---------------
__device__ float g_y1g[BATCH*192*NPIX];
__device__ float g_y1c[BATCH*24*NPIX];
__device__ float g_mg [BATCH*144*NPIX];
__device__ float g_mc [BATCH*108*NPIX];
__device__ float g_g8 [BATCH*96*NPIX];
__device__ float g_c8 [BATCH*12*NPIX];
__device__ unsigned g_wc1hi[27*192*16];
__device__ unsigned g_wc1lo[27*192*16];
__device__ unsigned g_w2hi [6*144*16];
__device__ unsigned g_w2lo [6*144*16];

// ===================== small helpers ========================================
__device__ __forceinline__ unsigned smem_u32(const void* p){
    unsigned a;
    asm("{ .reg .u64 t; cvta.to.shared.u64 t, %1; cvt.u32.u64 %0, t; }"
        : "=r"(a) : "l"(p));
    return a;
}
__device__ __forceinline__ unsigned short bf16hi(float x){
    unsigned u = __float_as_uint(x);
    unsigned r = u + 0x7fffu + ((u >> 16) & 1u);
    return (unsigned short)(r >> 16);
}
__device__ __forceinline__ float bf16f(unsigned short h){
    return __uint_as_float(((unsigned)h) << 16);
}
__device__ __forceinline__ unsigned pack2(unsigned short a, unsigned short b){
    return (unsigned)a | ((unsigned)b << 16);
}
__device__ __forceinline__ void ldm4(unsigned* r, unsigned addr){
    asm volatile("ldmatrix.sync.aligned.m8n8.x4.shared.b16 {%0,%1,%2,%3}, [%4];"
        : "=r"(r[0]), "=r"(r[1]), "=r"(r[2]), "=r"(r[3]) : "r"(addr));
}
__device__ __forceinline__ void mma_bf16(float* c, const unsigned* a,
                                         unsigned b0, unsigned b1){
    asm volatile("mma.sync.aligned.m16n8k16.row.col.f32.bf16.bf16.f32 "
        "{%0,%1,%2,%3}, {%4,%5,%6,%7}, {%8,%9}, {%0,%1,%2,%3};"
        : "+f"(c[0]), "+f"(c[1]), "+f"(c[2]), "+f"(c[3])
        : "r"(a[0]), "r"(a[1]), "r"(a[2]), "r"(a[3]), "r"(b0), "r"(b1));
}

// ===================== weight prep (both matrices, one launch) ===============
__global__ __launch_bounds__(256) void wprep(const float* __restrict__ w1,
                                             const float* __restrict__ w2,
                                             unsigned* __restrict__ w1hi,
                                             unsigned* __restrict__ w1lo,
                                             unsigned* __restrict__ w2hi,
                                             unsigned* __restrict__ w2lo)
{
    int idx = blockIdx.x * 256 + threadIdx.x;
    if (idx < 27*192*16) {
        int kk = idx & 15;
        int row = (idx >> 4) % 192;
        int c   = idx / (192*16);
        int k0 = c*32 + 2*kk, k1 = k0 + 1;
        int tap0 = k0 / 96, ic0 = k0 - tap0*96;
        int tap1 = k1 / 96, ic1 = k1 - tap1*96;
        float v0 = w1[row*864 + ic0*9 + tap0];
        float v1 = w1[row*864 + ic1*9 + tap1];
        unsigned short h0 = bf16hi(v0), h1 = bf16hi(v1);
        w1hi[idx] = pack2(h0, h1);
        w1lo[idx] = pack2(bf16hi(v0 - bf16f(h0)), bf16hi(v1 - bf16f(h1)));
    } else {
        int j = idx - 27*192*16;
        if (j >= 6*144*16) return;
        int kk = j & 15;
        int row = (j >> 4) % 144;
        int c   = j / (144*16);
        int k0 = c*32 + 2*kk;
        float v0 = w2[row*192 + k0];
        float v1 = w2[row*192 + k0 + 1];
        unsigned short h0 = bf16hi(v0), h1 = bf16hi(v1);
        w2hi[j] = pack2(h0, h1);
        w2lo[j] = pack2(bf16hi(v0 - bf16f(h0)), bf16hi(v1 - bf16f(h1)));
    }
}

// ===================== stage1: conv1 gwc(MMA) + conv1 cat(fused grid) ========
#define C1_A_HI 1536
#define C1_A_LO (C1_A_HI + 10240)
#define C1_B_HI (C1_A_LO + 10240)
#define C1_B_LO (C1_B_HI + 15360)
#define SMEM_S1 62640   // max(52736 gwc, 12*1089*4 + 2592*4 cat)

__global__ __launch_bounds__(256, 1) void stage1(
    const float* __restrict__ x,
    const unsigned* __restrict__ whi, const unsigned* __restrict__ wlo,
    const float* __restrict__ bng, const float* __restrict__ bnb,
    const float* __restrict__ bnm, const float* __restrict__ bnv,
    float* __restrict__ y,
    const float* __restrict__ xc_in, const float* __restrict__ wc,
    const float* __restrict__ cbg, const float* __restrict__ cbb,
    const float* __restrict__ cbm, const float* __restrict__ cbv,
    float* __restrict__ yc)
{
    extern __shared__ char smem[];
    const int tid = threadIdx.x;

    if (blockIdx.x < 360) {
        // ================= gwc conv1 MMA path =================
        const unsigned sb = smem_u32(smem);
        const int wid = tid >> 5, lane = tid & 31;
        float* sbn = (float*)smem;

        if (tid < 192) {
            float s = bng[tid] * rsqrtf(bnv[tid] + EPSV);
            sbn[tid] = s;
            sbn[192 + tid] = bnb[tid] - bnm[tid] * s;
        }

        const int m = tid & 127;
        const int khalf = tid >> 7;
        const int p  = blockIdx.x*128 + m;
        const int b  = p / NPIX;
        const int r  = p - b*NPIX;
        const int ho = r / WO, wo = r - (r/WO)*WO;
        const float* xb = x + (size_t)b * 96 * H_IN * W_IN;

        const int brow4 = tid >> 2, bq4 = (tid & 3)*4;

        const int wm = wid & 1, wn = wid >> 1;
        const unsigned aHiB = sb + C1_A_HI + ((wm*64 + (lane&15))*40 + (lane>>4)*8)*2;
        const unsigned aLoB = aHiB + 10240;
        const unsigned bHiB = sb + C1_B_HI + ((wn*48 + (lane&15))*40 + (lane>>4)*8)*2;
        const unsigned bLoB = bHiB + 15360;

        unsigned* sAhi = (unsigned*)(smem + C1_A_HI);
        unsigned* sAlo = (unsigned*)(smem + C1_A_LO);

        float acc[4][6][4];
        #pragma unroll
        for (int f = 0; f < 4; ++f)
            #pragma unroll
            for (int g = 0; g < 6; ++g)
                #pragma unroll
                for (int i = 0; i < 4; ++i) acc[f][g][i] = 0.f;

        float av[16];
        uint4 bhv[3], blv[3];

        {
            int ih = 2*ho - 1, iw = 2*wo - 1;
            bool ok = (ih >= 0) && (iw >= 0);
            const float* ptr = xb + ((size_t)(khalf*16)*H_IN + ih)*W_IN + iw;
            #pragma unroll
            for (int j = 0; j < 16; ++j)
                av[j] = ok ? __ldg(ptr + (size_t)j*H_IN*W_IN) : 0.f;
            #pragma unroll
            for (int it = 0; it < 3; ++it) {
                int e = (brow4 + it*64)*16 + bq4;
                bhv[it] = __ldg((const uint4*)(whi + e));
                blv[it] = __ldg((const uint4*)(wlo + e));
            }
        }

        for (int c = 0; c < 27; ++c) {
            {
                int wbase = m*20 + khalf*8;
                #pragma unroll
                for (int jj = 0; jj < 8; ++jj) {
                    float v0 = av[2*jj], v1 = av[2*jj+1];
                    unsigned short h0 = bf16hi(v0), h1 = bf16hi(v1);
                    unsigned short l0 = bf16hi(v0 - bf16f(h0));
                    unsigned short l1 = bf16hi(v1 - bf16f(h1));
                    sAhi[wbase + jj] = pack2(h0, h1);
                    sAlo[wbase + jj] = pack2(l0, l1);
                }
                #pragma unroll
                for (int it = 0; it < 3; ++it) {
                    int so = ((brow4 + it*64)*20 + bq4)*4;
                    *(uint4*)(smem + C1_B_HI + so) = bhv[it];
                    *(uint4*)(smem + C1_B_LO + so) = blv[it];
                }
            }
            __syncthreads();

            if (c < 26) {
                int cn = c + 1;
                int tap = cn / 3;
                int ic0 = (cn - tap*3)*32 + khalf*16;
                int ki = tap / 3, kj = tap - ki*3;
                int ih = 2*ho - 1 + ki, iw = 2*wo - 1 + kj;
                bool ok = (ih >= 0) && (iw >= 0);
                const float* ptr = xb + ((size_t)ic0*H_IN + ih)*W_IN + iw;
                #pragma unroll
                for (int j = 0; j < 16; ++j)
                    av[j] = ok ? __ldg(ptr + (size_t)j*H_IN*W_IN) : 0.f;
                #pragma unroll
                for (int it = 0; it < 3; ++it) {
                    int e = (cn*192 + brow4 + it*64)*16 + bq4;
                    bhv[it] = __ldg((const uint4*)(whi + e));
                    blv[it] = __ldg((const uint4*)(wlo + e));
                }
            }

            #pragma unroll
            for (int kst = 0; kst < 2; ++kst) {
                unsigned ko = kst*32;
                unsigned ah[4][4], al[4][4];
                #pragma unroll
                for (int f = 0; f < 4; ++f) {
                    ldm4(ah[f], aHiB + f*1280 + ko);
                    ldm4(al[f], aLoB + f*1280 + ko);
                }
                #pragma unroll
                for (int g2 = 0; g2 < 3; ++g2) {
                    unsigned bh[4], bl[4];
                    ldm4(bh, bHiB + g2*1280 + ko);
                    ldm4(bl, bLoB + g2*1280 + ko);
                    #pragma unroll
                    for (int f = 0; f < 4; ++f) {
                        mma_bf16(acc[f][2*g2],   ah[f], bh[0], bh[2]);
                        mma_bf16(acc[f][2*g2+1], ah[f], bh[1], bh[3]);
                        mma_bf16(acc[f][2*g2],   ah[f], bl[0], bl[2]);
                        mma_bf16(acc[f][2*g2+1], ah[f], bl[1], bl[3]);
                        mma_bf16(acc[f][2*g2],   al[f], bh[0], bh[2]);
                        mma_bf16(acc[f][2*g2+1], al[f], bh[1], bh[3]);
                    }
                }
            }
            __syncthreads();
        }

        float* sEpi = (float*)(smem + C1_A_HI);
        #pragma unroll
        for (int half = 0; half < 2; ++half) {
            if (wm == half) {
                #pragma unroll
                for (int f = 0; f < 4; ++f) {
                    int row0 = f*16 + (lane >> 2);
                    #pragma unroll
                    for (int g = 0; g < 6; ++g) {
                        int col0 = wn*48 + g*8 + 2*(lane & 3);
                        float s0 = sbn[col0],     b0v = sbn[192 + col0];
                        float s1 = sbn[col0 + 1], b1v = sbn[192 + col0 + 1];
                        float v;
                        v = acc[f][g][0]*s0 + b0v; v = v >= 0.f ? v : 0.1f*v; sEpi[ row0   *193 + col0  ] = v;
                        v = acc[f][g][1]*s1 + b1v; v = v >= 0.f ? v : 0.1f*v; sEpi[ row0   *193 + col0+1] = v;
                        v = acc[f][g][2]*s0 + b0v; v = v >= 0.f ? v : 0.1f*v; sEpi[(row0+8)*193 + col0  ] = v;
                        v = acc[f][g][3]*s1 + b1v; v = v >= 0.f ? v : 0.1f*v; sEpi[(row0+8)*193 + col0+1] = v;
                    }
                }
            }
            __syncthreads();
            int p0 = blockIdx.x*128 + half*64;
            int bb = p0 / NPIX;
            int rb = p0 - bb*NPIX;
            #pragma unroll 4
            for (int i = 0; i < 48; ++i) {
                int idx = tid + i*256;
                int mm = idx & 63, oc = idx >> 6;
                y[((size_t)bb*192 + oc)*NPIX + rb + mm] = sEpi[mm*193 + oc];
            }
            __syncthreads();
        }
    } else {
        // ================= cat conv1 path (single smem fill) =================
        float* s_in = (float*)smem;            // 12*1089 floats
        float* s_w  = s_in + 12*1089;          // 2592 floats
        int bid = blockIdx.x - 360;
        int b  = bid / 45;
        int rr = bid - b*45;
        int ho0 = (rr / 9) * 16, wo0 = (rr - (rr/9)*9) * 16;
        const int ty = tid >> 4, tx = tid & 15;
        const int ih0 = 2*ho0 - 1, iw0 = 2*wo0 - 1;

        const float* xb = xc_in + (size_t)b * 12 * H_IN * W_IN;
        for (int i = tid; i < 12*1089; i += 256) {
            int ic = i / 1089, j = i - ic*1089;
            int r2 = j / 33, c2 = j - r2*33;
            int ih = ih0 + r2, iw = iw0 + c2;
            s_in[i] = (ih >= 0 && ih < H_IN && iw >= 0 && iw < W_IN)
                      ? __ldg(xb + (size_t)ic*H_IN*W_IN + ih*W_IN + iw) : 0.f;
        }
        for (int i = tid; i < 2592; i += 256) s_w[i] = __ldg(wc + i);
        __syncthreads();

        float acc[24];
        #pragma unroll
        for (int o = 0; o < 24; ++o) acc[o] = 0.f;

        for (int ic = 0; ic < 12; ++ic) {
            float v[3][3];
            #pragma unroll
            for (int ki = 0; ki < 3; ++ki)
                #pragma unroll
                for (int kj = 0; kj < 3; ++kj)
                    v[ki][kj] = s_in[ic*1089 + (2*ty + ki)*33 + 2*tx + kj];
            #pragma unroll
            for (int o = 0; o < 24; ++o) {
                float a = acc[o];
                #pragma unroll
                for (int ki = 0; ki < 3; ++ki)
                    #pragma unroll
                    for (int kj = 0; kj < 3; ++kj)
                        a += s_w[(o*12 + ic)*9 + ki*3 + kj] * v[ki][kj];
                acc[o] = a;
            }
        }

        const int ho = ho0 + ty, wo = wo0 + tx;
        #pragma unroll
        for (int o = 0; o < 24; ++o) {
            float s    = __ldg(cbg + o) * rsqrtf(__ldg(cbv + o) + EPSV);
            float bias = __ldg(cbb + o) - __ldg(cbm + o) * s;
            float vv = acc[o] * s + bias;
            vv = vv >= 0.f ? vv : 0.1f * vv;
            yc[((size_t)b*24 + o)*NPIX + ho*WO + wo] = vv;
        }
    }
}

// ===================== stage2: mask gwc(MMA+softmax) + mask cat ==============
#define MKA_HI 0
#define MKA_LO 10240
#define MKB_HI 20480
#define MKB_LO 32000
#define SMEM_S2 (128*145*4)

__global__ __launch_bounds__(256, 1) void stage2(
    const float* __restrict__ y1,
    const unsigned* __restrict__ whi, const unsigned* __restrict__ wlo,
    float* __restrict__ mask,
    const float* __restrict__ y1c, const float* __restrict__ w2c,
    float* __restrict__ maskc)
{
    extern __shared__ char smem[];
    const int tid = threadIdx.x;

    if (blockIdx.x < 360) {
        const unsigned sb = smem_u32(smem);
        const int wid = tid >> 5, lane = tid & 31;
        const int p0 = blockIdx.x * 128;
        const int b  = p0 / NPIX;
        const int pp = p0 - b*NPIX;
        const float* yb = y1 + (size_t)b*192*NPIX + pp;

        unsigned* sAhi = (unsigned*)(smem + MKA_HI);
        unsigned* sAlo = (unsigned*)(smem + MKA_LO);

        const int am  = tid & 127, ahb = tid >> 7;
        const int brow4 = tid >> 2, bq4 = (tid & 3)*4;

        const unsigned aB = sb + MKA_HI + ((wid*16 + (lane&15))*40 + (lane>>4)*8)*2;
        const unsigned bB = sb + MKB_HI + (((lane&15))*40 + (lane>>4)*8)*2;

        float acc[18][4];
        #pragma unroll
        for (int j = 0; j < 18; ++j)
            #pragma unroll
            for (int i = 0; i < 4; ++i) acc[j][i] = 0.f;

        float av[16];
        uint4 bhv[3], blv[3];

        #pragma unroll
        for (int i = 0; i < 8; ++i) {
            int q = ahb + 2*i;
            av[2*i]   = __ldg(yb + (size_t)(2*q)  *NPIX + am);
            av[2*i+1] = __ldg(yb + (size_t)(2*q+1)*NPIX + am);
        }
        #pragma unroll
        for (int it = 0; it < 3; ++it) {
            int row = brow4 + it*64;
            if (row < 144) {
                int e = row*16 + bq4;
                bhv[it] = __ldg((const uint4*)(whi + e));
                blv[it] = __ldg((const uint4*)(wlo + e));
            }
        }

        for (int c = 0; c < 6; ++c) {
            #pragma unroll
            for (int i = 0; i < 8; ++i) {
                int q = ahb + 2*i;
                float v0 = av[2*i], v1 = av[2*i+1];
                unsigned short h0 = bf16hi(v0), h1 = bf16hi(v1);
                unsigned short l0 = bf16hi(v0 - bf16f(h0));
                unsigned short l1 = bf16hi(v1 - bf16f(h1));
                sAhi[am*20 + q] = pack2(h0, h1);
                sAlo[am*20 + q] = pack2(l0, l1);
            }
            #pragma unroll
            for (int it = 0; it < 3; ++it) {
                int row = brow4 + it*64;
                if (row < 144) {
                    int so = (row*20 + bq4)*4;
                    *(uint4*)(smem + MKB_HI + so) = bhv[it];
                    *(uint4*)(smem + MKB_LO + so) = blv[it];
                }
            }
            __syncthreads();

            if (c < 5) {
                int kb = (c + 1) * 32;
                #pragma unroll
                for (int i = 0; i < 8; ++i) {
                    int q = ahb + 2*i;
                    av[2*i]   = __ldg(yb + (size_t)(kb + 2*q)  *NPIX + am);
                    av[2*i+1] = __ldg(yb + (size_t)(kb + 2*q+1)*NPIX + am);
                }
                #pragma unroll
                for (int it = 0; it < 3; ++it) {
                    int row = brow4 + it*64;
                    if (row < 144) {
                        int e = ((c+1)*144 + row)*16 + bq4;
                        bhv[it] = __ldg((const uint4*)(whi + e));
                        blv[it] = __ldg((const uint4*)(wlo + e));
                    }
                }
            }

            #pragma unroll
            for (int ks = 0; ks < 2; ++ks) {
                unsigned ko = ks*32;
                unsigned ah[4], al[4];
                ldm4(ah, aB + ko);
                ldm4(al, aB + (MKA_LO - MKA_HI) + ko);
                #pragma unroll
                for (int jp = 0; jp < 9; ++jp) {
                    unsigned bh[4], bl[4];
                    ldm4(bh, bB + jp*1280 + ko);
                    ldm4(bl, bB + (MKB_LO - MKB_HI) + jp*1280 + ko);
                    mma_bf16(acc[2*jp],   ah, bh[0], bh[2]);
                    mma_bf16(acc[2*jp+1], ah, bh[1], bh[3]);
                    mma_bf16(acc[2*jp],   ah, bl[0], bl[2]);
                    mma_bf16(acc[2*jp+1], ah, bl[1], bl[3]);
                    mma_bf16(acc[2*jp],   al, bh[0], bh[2]);
                    mma_bf16(acc[2*jp+1], al, bh[1], bh[3]);
                }
            }
            __syncthreads();
        }

        float* sC = (float*)smem;
        {
            int r0 = wid*16 + (lane >> 2);
            #pragma unroll
            for (int j = 0; j < 18; ++j) {
                int c0 = j*8 + 2*(lane & 3);
                sC[ r0   *145 + c0  ] = acc[j][0];
                sC[ r0   *145 + c0+1] = acc[j][1];
                sC[(r0+8)*145 + c0  ] = acc[j][2];
                sC[(r0+8)*145 + c0+1] = acc[j][3];
            }
        }
        __syncthreads();

        const int sm = tid & 127;
        const float* srow = sC + sm*145;
        #pragma unroll
        for (int gi = 0; gi < 8; ++gi) {
            int g = (tid >> 7)*8 + gi;
            float v[9];
            #pragma unroll
            for (int j = 0; j < 9; ++j) v[j] = srow[g*9 + j];
            float mx = v[0];
            #pragma unroll
            for (int j = 1; j < 9; ++j) mx = fmaxf(mx, v[j]);
            float e[9], sum = 0.f;
            #pragma unroll
            for (int j = 0; j < 9; ++j) { e[j] = __expf(v[j] - mx); sum += e[j]; }
            float rs = 1.f / sum;
            float* mrow = mask + ((size_t)b*144 + g*9)*NPIX + pp + sm;
            #pragma unroll
            for (int j = 0; j < 9; ++j) mrow[(size_t)j*NPIX] = e[j]*rs;
        }
    } else {
        // ===== cat mask: 1 thread = 1 pixel, all 12 groups =====
        float* s_w = (float*)smem;          // 108*24 floats
        for (int i = tid; i < 108*24; i += 256) s_w[i] = __ldg(w2c + i);
        __syncthreads();

        int p = (blockIdx.x - 360)*256 + tid;   // < BATCH*NPIX
        int b  = p / NPIX;
        int pp = p - b*NPIX;
        const float* yb = y1c + (size_t)b*24*NPIX + pp;
        float yv[24];
        #pragma unroll
        for (int k = 0; k < 24; ++k) yv[k] = __ldg(yb + (size_t)k*NPIX);

        #pragma unroll
        for (int g = 0; g < 12; ++g) {
            float lg[9];
            #pragma unroll
            for (int j = 0; j < 9; ++j) {
                const float* wr = s_w + (g*9 + j)*24;
                float a = 0.f;
                #pragma unroll
                for (int k = 0; k < 24; ++k) a += wr[k] * yv[k];
                lg[j] = a;
            }
            float mx = lg[0];
            #pragma unroll
            for (int j = 1; j < 9; ++j) mx = fmaxf(mx, lg[j]);
            float e[9], sum = 0.f;
            #pragma unroll
            for (int j = 0; j < 9; ++j) { e[j] = __expf(lg[j] - mx); sum += e[j]; }
            float rs = 1.f / sum;
            float* mrow = maskc + ((size_t)b*108 + g*9)*NPIX + pp;
            #pragma unroll
            for (int j = 0; j < 9; ++j) mrow[(size_t)j*NPIX] = e[j]*rs;
        }
    }
}

// ===================== stage3: aggregation (gwc + cat fused grid) ============
__global__ __launch_bounds__(256) void stage3(
    const float* __restrict__ xg, const float* __restrict__ mg,
    float* __restrict__ g8,
    const float* __restrict__ xc, const float* __restrict__ mc,
    float* __restrict__ c8)
{
    const int tid = threadIdx.x;
    if (blockIdx.x < 2880) {
        int idx = blockIdx.x * 256 + tid;   // BATCH*16*NPIX
        int wo = idx % WO;
        int t  = idx / WO;
        int ho = t % HO; t /= HO;
        int g  = t % 16;
        int b  = t / 16;

        const float* mb = mg + ((size_t)b*144 + g*9) * NPIX + ho*WO + wo;
        float mreg[9];
        #pragma unroll
        for (int j = 0; j < 9; ++j) mreg[j] = __ldg(mb + (size_t)j*NPIX);

        const float* xgg = xg + ((size_t)b*96 + g) * H_IN * W_IN;
        float* og = g8 + ((size_t)b*96 + g) * NPIX + ho*WO + wo;

        #pragma unroll
        for (int cc = 0; cc < 6; ++cc) {
            const float* xcc = xgg + (size_t)cc*16*H_IN*W_IN;
            float acc = 0.f;
            #pragma unroll
            for (int ki = 0; ki < 3; ++ki) {
                int ih = 2*ho - 1 + ki;
                bool okh = (ih >= 0) && (ih < H_IN);
                #pragma unroll
                for (int kj = 0; kj < 3; ++kj) {
                    int iw = 2*wo - 1 + kj;
                    float xv = (okh && iw >= 0 && iw < W_IN) ? __ldg(xcc + ih*W_IN + iw) : 0.f;
                    acc += mreg[ki*3 + kj] * xv;
                }
            }
            og[(size_t)cc*16*NPIX] = acc;
        }
    } else {
        int idx = (blockIdx.x - 2880) * 256 + tid;   // BATCH*12*NPIX
        int wo = idx % WO;
        int t  = idx / WO;
        int ho = t % HO; t /= HO;
        int c  = t % 12;
        int b  = t / 12;

        const float* xb = xc + ((size_t)b*12 + c) * H_IN * W_IN;
        const float* mb = mc + ((size_t)b*108 + c*9) * NPIX + ho*WO + wo;

        float acc = 0.f;
        #pragma unroll
        for (int ki = 0; ki < 3; ++ki) {
            int ih = 2*ho - 1 + ki;
            bool okh = (ih >= 0) && (ih < H_IN);
            #pragma unroll
            for (int kj = 0; kj < 3; ++kj) {
                int iw = 2*wo - 1 + kj;
                float xv = (okh && iw >= 0 && iw < W_IN) ? __ldg(xb + ih*W_IN + iw) : 0.f;
                acc += __ldg(mb + (ki*3 + kj)*NPIX) * xv;
            }
        }
        c8[idx] = acc;
    }
}

// ===================== stage4: cost volumes (gwc + cat fused grid) ===========
__global__ __launch_bounds__(144) void stage4(const float* __restrict__ g8,
                                              const float* __restrict__ c8,
                                              float* __restrict__ out)
{
    __shared__ float sbuf[12*WO];
    const int w = threadIdx.x;

    if (blockIdx.x < 2*8*HO) {
        int t = blockIdx.x;
        const int h  = t % HO; t /= HO;
        const int g  = t % 8;
        const int b2 = t / 8;

        const float* lp = g8 + ((size_t)(b2*96 + g*12)) * NPIX + h*WO;
        const float* rp = g8 + ((size_t)((b2+2)*96 + g*12)) * NPIX + h*WO;
        float lv[12];
        #pragma unroll
        for (int c = 0; c < 12; ++c) {
            lv[c] = lp[(size_t)c*NPIX + w];
            sbuf[c*WO + w] = rp[(size_t)c*NPIX + w];
        }
        __syncthreads();

        float* ob = out + ((size_t)(b2*32 + g)) * DISP * NPIX + h*WO + w;
        #pragma unroll 4
        for (int d = 0; d < DISP; ++d) {
            float val = 0.f;
            if (d <= w) {
                float s = 0.f;
                #pragma unroll
                for (int c = 0; c < 12; ++c) s += lv[c] * sbuf[c*WO + w - d];
                val = s * (1.f/12.f);
            }
            ob[(size_t)d*NPIX] = val;
        }
    } else {
        int t = blockIdx.x - 2*8*HO;        // 2*24*HO blocks
        const int h  = t % HO; t /= HO;
        const int ch = t % 24;
        const int b2 = t / 24;

        float* ob = out + ((size_t)(b2*32 + 8 + ch)) * DISP * NPIX + h*WO + w;
        if (ch < 12) {
            float vL = __ldg(c8 + ((size_t)(b2*12 + ch)) * NPIX + h*WO + w);
            #pragma unroll 4
            for (int d = 0; d < DISP; ++d)
                ob[(size_t)d*NPIX] = (w >= d) ? vL : 0.f;
        } else {
            sbuf[w] = __ldg(c8 + ((size_t)((b2+2)*12 + (ch-12))) * NPIX + h*WO + w);
            __syncthreads();
            #pragma unroll 4
            for (int d = 0; d < DISP; ++d)
                ob[(size_t)d*NPIX] = (w >= d) ? sbuf[w - d] : 0.f;
        }
    }
}

// ------------------- launch --------------------------------------------------
extern "C" void kernel_launch(void* const* d_in, const int* in_sizes, int n_in,
                              void* d_out, int out_size)
{
    const float* gwc_f = (const float*)d_in[0];
    const float* cat_f = (const float*)d_in[1];
    const float* g_w1  = (const float*)d_in[2];
    const float* g_bg  = (const float*)d_in[3];
    const float* g_bb  = (const float*)d_in[4];
    const float* g_bm  = (const float*)d_in[5];
    const float* g_bv  = (const float*)d_in[6];
    const float* g_w2  = (const float*)d_in[7];
    const float* c_w1  = (const float*)d_in[8];
    const float* c_bg  = (const float*)d_in[9];
    const float* c_bb  = (const float*)d_in[10];
    const float* c_bm  = (const float*)d_in[11];
    const float* c_bv  = (const float*)d_in[12];
    const float* c_w2  = (const float*)d_in[13];
    float* out = (float*)d_out;

    float *y1g, *y1c, *mg, *mc, *g8, *c8;
    unsigned *wc1hi, *wc1lo, *w2hi, *w2lo;
    cudaGetSymbolAddress((void**)&y1g, g_y1g);
    cudaGetSymbolAddress((void**)&y1c, g_y1c);
    cudaGetSymbolAddress((void**)&mg,  g_mg);
    cudaGetSymbolAddress((void**)&mc,  g_mc);
    cudaGetSymbolAddress((void**)&g8,  g_g8);
    cudaGetSymbolAddress((void**)&c8,  g_c8);
    cudaGetSymbolAddress((void**)&wc1hi, g_wc1hi);
    cudaGetSymbolAddress((void**)&wc1lo, g_wc1lo);
    cudaGetSymbolAddress((void**)&w2hi,  g_w2hi);
    cudaGetSymbolAddress((void**)&w2lo,  g_w2lo);

    // 0) weight prep (one launch)
    wprep<<<(27*192*16 + 6*144*16 + 255)/256, 256>>>(g_w1, g_w2, wc1hi, wc1lo, w2hi, w2lo);

    // 1) conv1 gwc (MMA) + conv1 cat
    cudaFuncSetAttribute(stage1, cudaFuncAttributeMaxDynamicSharedMemorySize, SMEM_S1);
    stage1<<<360 + BATCH*45, 256, SMEM_S1>>>(gwc_f, wc1hi, wc1lo, g_bg, g_bb, g_bm, g_bv, y1g,
                                             cat_f, c_w1, c_bg, c_bb, c_bm, c_bv, y1c);

    // 2) mask gwc (MMA + softmax) + mask cat
    cudaFuncSetAttribute(stage2, cudaFuncAttributeMaxDynamicSharedMemorySize, SMEM_S2);
    stage2<<<360 + (BATCH*NPIX)/256, 256, SMEM_S2>>>(y1g, w2hi, w2lo, mg, y1c, c_w2, mc);

    // 3) aggregation
    stage3<<<2880 + 2160, 256>>>(gwc_f, mg, g8, cat_f, mc, c8);

    // 4) cost volumes
    stage4<<<2*8*HO + 2*24*HO, 144>>>(g8, c8, out);
}

// round 8
// speedup vs baseline: 2.8710x; 1.0580x over previous
#include <cuda_runtime.h>
#include <cstdint>

#define H_IN 160
#define W_IN 288
#define HO   80
#define WO   144
#define NPIX (HO*WO)          // 11520
#define BATCH 4
#define EPSV 1e-5f
#define DISP 24

// ------------------- scratch (static device memory, no allocs) ---------------
__device__ float g_y1g[BATCH*192*NPIX];
__device__ float g_y1c[BATCH*24*NPIX];
__device__ float g_mg [BATCH*144*NPIX];
__device__ float g_mc [BATCH*108*NPIX];
__device__ float g_g8 [BATCH*96*NPIX];
__device__ float g_c8 [BATCH*12*NPIX];
__device__ unsigned g_wc1hi[27*192*16];
__device__ unsigned g_wc1lo[27*192*16];
__device__ unsigned g_w2hi [6*144*16];
__device__ unsigned g_w2lo [6*144*16];

// ===================== small helpers ========================================
__device__ __forceinline__ unsigned smem_u32(const void* p){
    unsigned a;
    asm("{ .reg .u64 t; cvta.to.shared.u64 t, %1; cvt.u32.u64 %0, t; }"
        : "=r"(a) : "l"(p));
    return a;
}
__device__ __forceinline__ unsigned short bf16hi(float x){
    unsigned u = __float_as_uint(x);
    unsigned r = u + 0x7fffu + ((u >> 16) & 1u);
    return (unsigned short)(r >> 16);
}
__device__ __forceinline__ float bf16f(unsigned short h){
    return __uint_as_float(((unsigned)h) << 16);
}
__device__ __forceinline__ unsigned pack2(unsigned short a, unsigned short b){
    return (unsigned)a | ((unsigned)b << 16);
}
__device__ __forceinline__ void ldm4(unsigned* r, unsigned addr){
    asm volatile("ldmatrix.sync.aligned.m8n8.x4.shared.b16 {%0,%1,%2,%3}, [%4];"
        : "=r"(r[0]), "=r"(r[1]), "=r"(r[2]), "=r"(r[3]) : "r"(addr));
}
__device__ __forceinline__ void mma_bf16(float* c, const unsigned* a,
                                         unsigned b0, unsigned b1){
    asm volatile("mma.sync.aligned.m16n8k16.row.col.f32.bf16.bf16.f32 "
        "{%0,%1,%2,%3}, {%4,%5,%6,%7}, {%8,%9}, {%0,%1,%2,%3};"
        : "+f"(c[0]), "+f"(c[1]), "+f"(c[2]), "+f"(c[3])
        : "r"(a[0]), "r"(a[1]), "r"(a[2]), "r"(a[3]), "r"(b0), "r"(b1));
}

// ===================== weight prep ==========================================
__global__ __launch_bounds__(256) void wprep(const float* __restrict__ w1,
                                             const float* __restrict__ w2,
                                             unsigned* __restrict__ w1hi,
                                             unsigned* __restrict__ w1lo,
                                             unsigned* __restrict__ w2hi,
                                             unsigned* __restrict__ w2lo)
{
    int idx = blockIdx.x * 256 + threadIdx.x;
    if (idx < 27*192*16) {
        int kk = idx & 15;
        int row = (idx >> 4) % 192;
        int c   = idx / (192*16);
        int k0 = c*32 + 2*kk, k1 = k0 + 1;
        int tap0 = k0 / 96, ic0 = k0 - tap0*96;
        int tap1 = k1 / 96, ic1 = k1 - tap1*96;
        float v0 = w1[row*864 + ic0*9 + tap0];
        float v1 = w1[row*864 + ic1*9 + tap1];
        unsigned short h0 = bf16hi(v0), h1 = bf16hi(v1);
        w1hi[idx] = pack2(h0, h1);
        w1lo[idx] = pack2(bf16hi(v0 - bf16f(h0)), bf16hi(v1 - bf16f(h1)));
    } else {
        int j = idx - 27*192*16;
        if (j >= 6*144*16) return;
        int kk = j & 15;
        int row = (j >> 4) % 144;
        int c   = j / (144*16);
        int k0 = c*32 + 2*kk;
        float v0 = w2[row*192 + k0];
        float v1 = w2[row*192 + k0 + 1];
        unsigned short h0 = bf16hi(v0), h1 = bf16hi(v1);
        w2hi[j] = pack2(h0, h1);
        w2lo[j] = pack2(bf16hi(v0 - bf16f(h0)), bf16hi(v1 - bf16f(h1)));
    }
}

// ===================== stage1: conv1 gwc(MMA,512thr) + conv1 cat =============
#define C1_A_HI 1536
#define C1_A_LO (C1_A_HI + 10240)
#define C1_B_HI (C1_A_LO + 10240)
#define C1_B_LO (C1_B_HI + 15360)
#define SMEM_S1 62640

__global__ __launch_bounds__(512, 1) void stage1(
    const float* __restrict__ x,
    const unsigned* __restrict__ whi, const unsigned* __restrict__ wlo,
    const float* __restrict__ bng, const float* __restrict__ bnb,
    const float* __restrict__ bnm, const float* __restrict__ bnv,
    float* __restrict__ y,
    const float* __restrict__ xc_in, const float* __restrict__ wc,
    const float* __restrict__ cbg, const float* __restrict__ cbb,
    const float* __restrict__ cbm, const float* __restrict__ cbv,
    float* __restrict__ yc)
{
    extern __shared__ char smem[];
    const int tid = threadIdx.x;

    if (blockIdx.x < 360) {
        // ================= gwc conv1 MMA, 16 warps: 4 wm x 4 wn =================
        const unsigned sb = smem_u32(smem);
        const int wid = tid >> 5, lane = tid & 31;
        float* sbn = (float*)smem;

        if (tid < 192) {
            float s = bng[tid] * rsqrtf(bnv[tid] + EPSV);
            sbn[tid] = s;
            sbn[192 + tid] = bnb[tid] - bnm[tid] * s;
        }

        // A gather: 4 threads per pixel row, 8 ic each
        const int m  = tid & 127;
        const int kq = tid >> 7;                 // 0..3
        const int p  = blockIdx.x*128 + m;
        const int b  = p / NPIX;
        const int r  = p - b*NPIX;
        const int ho = r / WO, wo = r - (r/WO)*WO;
        const float* xb = x + (size_t)b * 96 * H_IN * W_IN;

        // B copy: rows tid>>2 (and +128 if tid<256), uint4 each
        const int brow = tid >> 2, bq4 = (tid & 3)*4;

        const int wm = wid & 3, wn = wid >> 2;
        const unsigned aHiB = sb + C1_A_HI + ((wm*32 + (lane&15))*40 + (lane>>4)*8)*2;
        const unsigned aLoB = aHiB + 10240;
        const unsigned bHiB = sb + C1_B_HI + ((wn*48 + (lane&15))*40 + (lane>>4)*8)*2;
        const unsigned bLoB = bHiB + 15360;

        unsigned* sAhi = (unsigned*)(smem + C1_A_HI);
        unsigned* sAlo = (unsigned*)(smem + C1_A_LO);

        float acc[2][6][4];
        #pragma unroll
        for (int f = 0; f < 2; ++f)
            #pragma unroll
            for (int g = 0; g < 6; ++g)
                #pragma unroll
                for (int i = 0; i < 4; ++i) acc[f][g][i] = 0.f;

        float av[8];
        uint4 bhv[2], blv[2];

        {   // prefetch chunk 0
            int ih = 2*ho - 1, iw = 2*wo - 1;
            bool ok = (ih >= 0) && (iw >= 0);
            const float* ptr = xb + ((size_t)(kq*8)*H_IN + ih)*W_IN + iw;
            #pragma unroll
            for (int j = 0; j < 8; ++j)
                av[j] = ok ? __ldg(ptr + (size_t)j*H_IN*W_IN) : 0.f;
            bhv[0] = __ldg((const uint4*)(whi + brow*16 + bq4));
            blv[0] = __ldg((const uint4*)(wlo + brow*16 + bq4));
            if (tid < 256) {
                bhv[1] = __ldg((const uint4*)(whi + (128 + brow)*16 + bq4));
                blv[1] = __ldg((const uint4*)(wlo + (128 + brow)*16 + bq4));
            }
        }

        for (int c = 0; c < 27; ++c) {
            {   // STS A (convert) + B (copy)
                int wbase = m*20 + kq*4;
                #pragma unroll
                for (int jj = 0; jj < 4; ++jj) {
                    float v0 = av[2*jj], v1 = av[2*jj+1];
                    unsigned short h0 = bf16hi(v0), h1 = bf16hi(v1);
                    unsigned short l0 = bf16hi(v0 - bf16f(h0));
                    unsigned short l1 = bf16hi(v1 - bf16f(h1));
                    sAhi[wbase + jj] = pack2(h0, h1);
                    sAlo[wbase + jj] = pack2(l0, l1);
                }
                int so = (brow*20 + bq4)*4;
                *(uint4*)(smem + C1_B_HI + so) = bhv[0];
                *(uint4*)(smem + C1_B_LO + so) = blv[0];
                if (tid < 256) {
                    int so2 = ((128 + brow)*20 + bq4)*4;
                    *(uint4*)(smem + C1_B_HI + so2) = bhv[1];
                    *(uint4*)(smem + C1_B_LO + so2) = blv[1];
                }
            }
            __syncthreads();

            if (c < 26) {   // prefetch next chunk
                int cn = c + 1;
                int tap = cn / 3;
                int ic0 = (cn - tap*3)*32 + kq*8;
                int ki = tap / 3, kj = tap - ki*3;
                int ih = 2*ho - 1 + ki, iw = 2*wo - 1 + kj;
                bool ok = (ih >= 0) && (iw >= 0);
                const float* ptr = xb + ((size_t)ic0*H_IN + ih)*W_IN + iw;
                #pragma unroll
                for (int j = 0; j < 8; ++j)
                    av[j] = ok ? __ldg(ptr + (size_t)j*H_IN*W_IN) : 0.f;
                bhv[0] = __ldg((const uint4*)(whi + (cn*192 + brow)*16 + bq4));
                blv[0] = __ldg((const uint4*)(wlo + (cn*192 + brow)*16 + bq4));
                if (tid < 256) {
                    bhv[1] = __ldg((const uint4*)(whi + (cn*192 + 128 + brow)*16 + bq4));
                    blv[1] = __ldg((const uint4*)(wlo + (cn*192 + 128 + brow)*16 + bq4));
                }
            }

            #pragma unroll
            for (int kst = 0; kst < 2; ++kst) {
                unsigned ko = kst*32;
                unsigned ah[2][4], al[2][4];
                #pragma unroll
                for (int f = 0; f < 2; ++f) {
                    ldm4(ah[f], aHiB + f*1280 + ko);
                    ldm4(al[f], aLoB + f*1280 + ko);
                }
                #pragma unroll
                for (int g2 = 0; g2 < 3; ++g2) {
                    unsigned bh[4], bl[4];
                    ldm4(bh, bHiB + g2*1280 + ko);
                    ldm4(bl, bLoB + g2*1280 + ko);
                    #pragma unroll
                    for (int f = 0; f < 2; ++f) {
                        mma_bf16(acc[f][2*g2],   ah[f], bh[0], bh[2]);
                        mma_bf16(acc[f][2*g2+1], ah[f], bh[1], bh[3]);
                        mma_bf16(acc[f][2*g2],   ah[f], bl[0], bl[2]);
                        mma_bf16(acc[f][2*g2+1], ah[f], bl[1], bl[3]);
                        mma_bf16(acc[f][2*g2],   al[f], bh[0], bh[2]);
                        mma_bf16(acc[f][2*g2+1], al[f], bh[1], bh[3]);
                    }
                }
            }
            __syncthreads();
        }

        // epilogue: BN + leaky, two 64-row transpose passes
        float* sEpi = (float*)(smem + C1_A_HI);
        #pragma unroll
        for (int half = 0; half < 2; ++half) {
            if ((wm >> 1) == half) {
                #pragma unroll
                for (int f = 0; f < 2; ++f) {
                    int row0 = (wm & 1)*32 + f*16 + (lane >> 2);
                    #pragma unroll
                    for (int g = 0; g < 6; ++g) {
                        int col0 = wn*48 + g*8 + 2*(lane & 3);
                        float s0 = sbn[col0],     b0v = sbn[192 + col0];
                        float s1 = sbn[col0 + 1], b1v = sbn[192 + col0 + 1];
                        float v;
                        v = acc[f][g][0]*s0 + b0v; v = v >= 0.f ? v : 0.1f*v; sEpi[ row0   *193 + col0  ] = v;
                        v = acc[f][g][1]*s1 + b1v; v = v >= 0.f ? v : 0.1f*v; sEpi[ row0   *193 + col0+1] = v;
                        v = acc[f][g][2]*s0 + b0v; v = v >= 0.f ? v : 0.1f*v; sEpi[(row0+8)*193 + col0  ] = v;
                        v = acc[f][g][3]*s1 + b1v; v = v >= 0.f ? v : 0.1f*v; sEpi[(row0+8)*193 + col0+1] = v;
                    }
                }
            }
            __syncthreads();
            int p0 = blockIdx.x*128 + half*64;
            int bb = p0 / NPIX;
            int rb = p0 - bb*NPIX;
            #pragma unroll 4
            for (int i = 0; i < 24; ++i) {
                int idx = tid + i*512;
                int mm = idx & 63, oc = idx >> 6;
                y[((size_t)bb*192 + oc)*NPIX + rb + mm] = sEpi[mm*193 + oc];
            }
            __syncthreads();
        }
    } else {
        // ================= cat conv1 path =================
        float* s_in = (float*)smem;
        float* s_w  = s_in + 12*1089;
        int bid = blockIdx.x - 360;
        int b  = bid / 45;
        int rr = bid - b*45;
        int ho0 = (rr / 9) * 16, wo0 = (rr - (rr/9)*9) * 16;
        const int ih0 = 2*ho0 - 1, iw0 = 2*wo0 - 1;

        const float* xb = xc_in + (size_t)b * 12 * H_IN * W_IN;
        for (int i = tid; i < 12*1089; i += 512) {
            int ic = i / 1089, j = i - ic*1089;
            int r2 = j / 33, c2 = j - r2*33;
            int ih = ih0 + r2, iw = iw0 + c2;
            s_in[i] = (ih >= 0 && ih < H_IN && iw >= 0 && iw < W_IN)
                      ? __ldg(xb + (size_t)ic*H_IN*W_IN + ih*W_IN + iw) : 0.f;
        }
        for (int i = tid; i < 2592; i += 512) s_w[i] = __ldg(wc + i);
        __syncthreads();

        if (tid < 256) {
            const int ty = tid >> 4, tx = tid & 15;
            float acc[24];
            #pragma unroll
            for (int o = 0; o < 24; ++o) acc[o] = 0.f;

            for (int ic = 0; ic < 12; ++ic) {
                float v[3][3];
                #pragma unroll
                for (int ki = 0; ki < 3; ++ki)
                    #pragma unroll
                    for (int kj = 0; kj < 3; ++kj)
                        v[ki][kj] = s_in[ic*1089 + (2*ty + ki)*33 + 2*tx + kj];
                #pragma unroll
                for (int o = 0; o < 24; ++o) {
                    float a = acc[o];
                    #pragma unroll
                    for (int ki = 0; ki < 3; ++ki)
                        #pragma unroll
                        for (int kj = 0; kj < 3; ++kj)
                            a += s_w[(o*12 + ic)*9 + ki*3 + kj] * v[ki][kj];
                    acc[o] = a;
                }
            }

            const int ho = ho0 + ty, wo = wo0 + tx;
            #pragma unroll
            for (int o = 0; o < 24; ++o) {
                float s    = __ldg(cbg + o) * rsqrtf(__ldg(cbv + o) + EPSV);
                float bias = __ldg(cbb + o) - __ldg(cbm + o) * s;
                float vv = acc[o] * s + bias;
                vv = vv >= 0.f ? vv : 0.1f * vv;
                yc[((size_t)b*24 + o)*NPIX + ho*WO + wo] = vv;
            }
        }
    }
}

// ===================== stage2: mask gwc(MMA 768thr) + mask cat ===============
#define MKA_HI 0
#define MKA_LO 10240
#define MKB_HI 20480
#define MKB_LO 32000
#define SMEM_S2 (128*145*4)

__global__ __launch_bounds__(768, 1) void stage2(
    const float* __restrict__ y1,
    const unsigned* __restrict__ whi, const unsigned* __restrict__ wlo,
    float* __restrict__ mask,
    const float* __restrict__ y1c, const float* __restrict__ w2c,
    float* __restrict__ maskc)
{
    extern __shared__ char smem[];
    const int tid = threadIdx.x;

    if (blockIdx.x < 360) {
        const unsigned sb = smem_u32(smem);
        const int wid = tid >> 5, lane = tid & 31;
        const int p0 = blockIdx.x * 128;
        const int b  = p0 / NPIX;
        const int pp = p0 - b*NPIX;
        const float* yb = y1 + (size_t)b*192*NPIX + pp;

        unsigned* sAhi = (unsigned*)(smem + MKA_HI);
        unsigned* sAlo = (unsigned*)(smem + MKA_LO);

        // A gather: 6 phases over 16 k-pairs
        const int am = tid & 127, phase = tid >> 7;   // 0..5
        // B copy: 576 uint4 per matrix
        const int brow = tid >> 2, bq4 = (tid & 3)*4;
        const bool bok = tid < 576;

        const int wm = wid & 7, wn = wid >> 3;        // 16 rows x 48 cols
        const unsigned aB = sb + MKA_HI + ((wm*16 + (lane&15))*40 + (lane>>4)*8)*2;
        const unsigned bB = sb + MKB_HI + ((wn*48 + (lane&15))*40 + (lane>>4)*8)*2;

        float acc[6][4];
        #pragma unroll
        for (int j = 0; j < 6; ++j)
            #pragma unroll
            for (int i = 0; i < 4; ++i) acc[j][i] = 0.f;

        float av[6];
        uint4 bhv, blv;

        // prefetch chunk 0
        #pragma unroll
        for (int i = 0; i < 3; ++i) {
            int q = phase + 6*i;
            if (q < 16) {
                av[2*i]   = __ldg(yb + (size_t)(2*q)  *NPIX + am);
                av[2*i+1] = __ldg(yb + (size_t)(2*q+1)*NPIX + am);
            }
        }
        if (bok) {
            bhv = __ldg((const uint4*)(whi + brow*16 + bq4));
            blv = __ldg((const uint4*)(wlo + brow*16 + bq4));
        }

        for (int c = 0; c < 6; ++c) {
            #pragma unroll
            for (int i = 0; i < 3; ++i) {
                int q = phase + 6*i;
                if (q < 16) {
                    float v0 = av[2*i], v1 = av[2*i+1];
                    unsigned short h0 = bf16hi(v0), h1 = bf16hi(v1);
                    unsigned short l0 = bf16hi(v0 - bf16f(h0));
                    unsigned short l1 = bf16hi(v1 - bf16f(h1));
                    sAhi[am*20 + q] = pack2(h0, h1);
                    sAlo[am*20 + q] = pack2(l0, l1);
                }
            }
            if (bok) {
                int so = (brow*20 + bq4)*4;
                *(uint4*)(smem + MKB_HI + so) = bhv;
                *(uint4*)(smem + MKB_LO + so) = blv;
            }
            __syncthreads();

            if (c < 5) {
                int kb = (c + 1) * 32;
                #pragma unroll
                for (int i = 0; i < 3; ++i) {
                    int q = phase + 6*i;
                    if (q < 16) {
                        av[2*i]   = __ldg(yb + (size_t)(kb + 2*q)  *NPIX + am);
                        av[2*i+1] = __ldg(yb + (size_t)(kb + 2*q+1)*NPIX + am);
                    }
                }
                if (bok) {
                    bhv = __ldg((const uint4*)(whi + ((c+1)*144 + brow)*16 + bq4));
                    blv = __ldg((const uint4*)(wlo + ((c+1)*144 + brow)*16 + bq4));
                }
            }

            #pragma unroll
            for (int ks = 0; ks < 2; ++ks) {
                unsigned ko = ks*32;
                unsigned ah[4], al[4];
                ldm4(ah, aB + ko);
                ldm4(al, aB + (MKA_LO - MKA_HI) + ko);
                #pragma unroll
                for (int g2 = 0; g2 < 3; ++g2) {
                    unsigned bh[4], bl[4];
                    ldm4(bh, bB + g2*1280 + ko);
                    ldm4(bl, bB + (MKB_LO - MKB_HI) + g2*1280 + ko);
                    mma_bf16(acc[2*g2],   ah, bh[0], bh[2]);
                    mma_bf16(acc[2*g2+1], ah, bh[1], bh[3]);
                    mma_bf16(acc[2*g2],   ah, bl[0], bl[2]);
                    mma_bf16(acc[2*g2+1], ah, bl[1], bl[3]);
                    mma_bf16(acc[2*g2],   al, bh[0], bh[2]);
                    mma_bf16(acc[2*g2+1], al, bh[1], bh[3]);
                }
            }
            __syncthreads();
        }

        // logits to smem
        float* sC = (float*)smem;
        {
            int r0 = wm*16 + (lane >> 2);
            #pragma unroll
            for (int j = 0; j < 6; ++j) {
                int c0 = wn*48 + j*8 + 2*(lane & 3);
                sC[ r0   *145 + c0  ] = acc[j][0];
                sC[ r0   *145 + c0+1] = acc[j][1];
                sC[(r0+8)*145 + c0  ] = acc[j][2];
                sC[(r0+8)*145 + c0+1] = acc[j][3];
            }
        }
        __syncthreads();

        // softmax over 9 per (pixel, group)
        const int sm = tid & 127;
        const int gb = tid >> 7;
        const float* srow = sC + sm*145;
        #pragma unroll
        for (int i = 0; i < 3; ++i) {
            int g = gb + 6*i;
            if (g < 16) {
                float v[9];
                #pragma unroll
                for (int j = 0; j < 9; ++j) v[j] = srow[g*9 + j];
                float mx = v[0];
                #pragma unroll
                for (int j = 1; j < 9; ++j) mx = fmaxf(mx, v[j]);
                float e[9], sum = 0.f;
                #pragma unroll
                for (int j = 0; j < 9; ++j) { e[j] = __expf(v[j] - mx); sum += e[j]; }
                float rs = 1.f / sum;
                float* mrow = mask + ((size_t)b*144 + g*9)*NPIX + pp + sm;
                #pragma unroll
                for (int j = 0; j < 9; ++j) mrow[(size_t)j*NPIX] = e[j]*rs;
            }
        }
    } else {
        // ===== cat mask: 1 thread = 1 pixel, all 12 groups =====
        float* s_w = (float*)smem;
        for (int i = tid; i < 108*24; i += 768) s_w[i] = __ldg(w2c + i);
        __syncthreads();

        int p = (blockIdx.x - 360)*768 + tid;   // < BATCH*NPIX (60 blocks exact)
        int b  = p / NPIX;
        int pp = p - b*NPIX;
        const float* yb = y1c + (size_t)b*24*NPIX + pp;
        float yv[24];
        #pragma unroll
        for (int k = 0; k < 24; ++k) yv[k] = __ldg(yb + (size_t)k*NPIX);

        #pragma unroll
        for (int g = 0; g < 12; ++g) {
            float lg[9];
            #pragma unroll
            for (int j = 0; j < 9; ++j) {
                const float* wr = s_w + (g*9 + j)*24;
                float a = 0.f;
                #pragma unroll
                for (int k = 0; k < 24; ++k) a += wr[k] * yv[k];
                lg[j] = a;
            }
            float mx = lg[0];
            #pragma unroll
            for (int j = 1; j < 9; ++j) mx = fmaxf(mx, lg[j]);
            float e[9], sum = 0.f;
            #pragma unroll
            for (int j = 0; j < 9; ++j) { e[j] = __expf(lg[j] - mx); sum += e[j]; }
            float rs = 1.f / sum;
            float* mrow = maskc + ((size_t)b*108 + g*9)*NPIX + pp;
            #pragma unroll
            for (int j = 0; j < 9; ++j) mrow[(size_t)j*NPIX] = e[j]*rs;
        }
    }
}

// ===================== stage3: aggregation (gwc + cat fused grid) ============
__global__ __launch_bounds__(256) void stage3(
    const float* __restrict__ xg, const float* __restrict__ mg,
    float* __restrict__ g8,
    const float* __restrict__ xc, const float* __restrict__ mc,
    float* __restrict__ c8)
{
    const int tid = threadIdx.x;
    if (blockIdx.x < 2880) {
        int idx = blockIdx.x * 256 + tid;
        int wo = idx % WO;
        int t  = idx / WO;
        int ho = t % HO; t /= HO;
        int g  = t % 16;
        int b  = t / 16;

        const float* mb = mg + ((size_t)b*144 + g*9) * NPIX + ho*WO + wo;
        float mreg[9];
        #pragma unroll
        for (int j = 0; j < 9; ++j) mreg[j] = __ldg(mb + (size_t)j*NPIX);

        const float* xgg = xg + ((size_t)b*96 + g) * H_IN * W_IN;
        float* og = g8 + ((size_t)b*96 + g) * NPIX + ho*WO + wo;

        #pragma unroll
        for (int cc = 0; cc < 6; ++cc) {
            const float* xcc = xgg + (size_t)cc*16*H_IN*W_IN;
            float acc = 0.f;
            #pragma unroll
            for (int ki = 0; ki < 3; ++ki) {
                int ih = 2*ho - 1 + ki;
                bool okh = (ih >= 0) && (ih < H_IN);
                #pragma unroll
                for (int kj = 0; kj < 3; ++kj) {
                    int iw = 2*wo - 1 + kj;
                    float xv = (okh && iw >= 0 && iw < W_IN) ? __ldg(xcc + ih*W_IN + iw) : 0.f;
                    acc += mreg[ki*3 + kj] * xv;
                }
            }
            og[(size_t)cc*16*NPIX] = acc;
        }
    } else {
        int idx = (blockIdx.x - 2880) * 256 + tid;
        int wo = idx % WO;
        int t  = idx / WO;
        int ho = t % HO; t /= HO;
        int c  = t % 12;
        int b  = t / 12;

        const float* xb = xc + ((size_t)b*12 + c) * H_IN * W_IN;
        const float* mb = mc + ((size_t)b*108 + c*9) * NPIX + ho*WO + wo;

        float acc = 0.f;
        #pragma unroll
        for (int ki = 0; ki < 3; ++ki) {
            int ih = 2*ho - 1 + ki;
            bool okh = (ih >= 0) && (ih < H_IN);
            #pragma unroll
            for (int kj = 0; kj < 3; ++kj) {
                int iw = 2*wo - 1 + kj;
                float xv = (okh && iw >= 0 && iw < W_IN) ? __ldg(xb + ih*W_IN + iw) : 0.f;
                acc += __ldg(mb + (ki*3 + kj)*NPIX) * xv;
            }
        }
        c8[idx] = acc;
    }
}

// ===================== stage4: cost volumes (gwc + cat fused grid) ===========
__global__ __launch_bounds__(144) void stage4(const float* __restrict__ g8,
                                              const float* __restrict__ c8,
                                              float* __restrict__ out)
{
    __shared__ float sbuf[12*WO];
    const int w = threadIdx.x;

    if (blockIdx.x < 2*8*HO) {
        int t = blockIdx.x;
        const int h  = t % HO; t /= HO;
        const int g  = t % 8;
        const int b2 = t / 8;

        const float* lp = g8 + ((size_t)(b2*96 + g*12)) * NPIX + h*WO;
        const float* rp = g8 + ((size_t)((b2+2)*96 + g*12)) * NPIX + h*WO;
        float lv[12];
        #pragma unroll
        for (int c = 0; c < 12; ++c) {
            lv[c] = lp[(size_t)c*NPIX + w];
            sbuf[c*WO + w] = rp[(size_t)c*NPIX + w];
        }
        __syncthreads();

        float* ob = out + ((size_t)(b2*32 + g)) * DISP * NPIX + h*WO + w;
        #pragma unroll 4
        for (int d = 0; d < DISP; ++d) {
            float val = 0.f;
            if (d <= w) {
                float s = 0.f;
                #pragma unroll
                for (int c = 0; c < 12; ++c) s += lv[c] * sbuf[c*WO + w - d];
                val = s * (1.f/12.f);
            }
            ob[(size_t)d*NPIX] = val;
        }
    } else {
        int t = blockIdx.x - 2*8*HO;
        const int h  = t % HO; t /= HO;
        const int ch = t % 24;
        const int b2 = t / 24;

        float* ob = out + ((size_t)(b2*32 + 8 + ch)) * DISP * NPIX + h*WO + w;
        if (ch < 12) {
            float vL = __ldg(c8 + ((size_t)(b2*12 + ch)) * NPIX + h*WO + w);
            #pragma unroll 4
            for (int d = 0; d < DISP; ++d)
                ob[(size_t)d*NPIX] = (w >= d) ? vL : 0.f;
        } else {
            sbuf[w] = __ldg(c8 + ((size_t)((b2+2)*12 + (ch-12))) * NPIX + h*WO + w);
            __syncthreads();
            #pragma unroll 4
            for (int d = 0; d < DISP; ++d)
                ob[(size_t)d*NPIX] = (w >= d) ? sbuf[w - d] : 0.f;
        }
    }
}

// ------------------- launch --------------------------------------------------
extern "C" void kernel_launch(void* const* d_in, const int* in_sizes, int n_in,
                              void* d_out, int out_size)
{
    const float* gwc_f = (const float*)d_in[0];
    const float* cat_f = (const float*)d_in[1];
    const float* g_w1  = (const float*)d_in[2];
    const float* g_bg  = (const float*)d_in[3];
    const float* g_bb  = (const float*)d_in[4];
    const float* g_bm  = (const float*)d_in[5];
    const float* g_bv  = (const float*)d_in[6];
    const float* g_w2  = (const float*)d_in[7];
    const float* c_w1  = (const float*)d_in[8];
    const float* c_bg  = (const float*)d_in[9];
    const float* c_bb  = (const float*)d_in[10];
    const float* c_bm  = (const float*)d_in[11];
    const float* c_bv  = (const float*)d_in[12];
    const float* c_w2  = (const float*)d_in[13];
    float* out = (float*)d_out;

    float *y1g, *y1c, *mg, *mc, *g8, *c8;
    unsigned *wc1hi, *wc1lo, *w2hi, *w2lo;
    cudaGetSymbolAddress((void**)&y1g, g_y1g);
    cudaGetSymbolAddress((void**)&y1c, g_y1c);
    cudaGetSymbolAddress((void**)&mg,  g_mg);
    cudaGetSymbolAddress((void**)&mc,  g_mc);
    cudaGetSymbolAddress((void**)&g8,  g_g8);
    cudaGetSymbolAddress((void**)&c8,  g_c8);
    cudaGetSymbolAddress((void**)&wc1hi, g_wc1hi);
    cudaGetSymbolAddress((void**)&wc1lo, g_wc1lo);
    cudaGetSymbolAddress((void**)&w2hi,  g_w2hi);
    cudaGetSymbolAddress((void**)&w2lo,  g_w2lo);

    // 0) weight prep
    wprep<<<(27*192*16 + 6*144*16 + 255)/256, 256>>>(g_w1, g_w2, wc1hi, wc1lo, w2hi, w2lo);

    // 1) conv1 gwc (MMA, 512thr) + conv1 cat
    cudaFuncSetAttribute(stage1, cudaFuncAttributeMaxDynamicSharedMemorySize, SMEM_S1);
    stage1<<<360 + BATCH*45, 512, SMEM_S1>>>(gwc_f, wc1hi, wc1lo, g_bg, g_bb, g_bm, g_bv, y1g,
                                             cat_f, c_w1, c_bg, c_bb, c_bm, c_bv, y1c);

    // 2) mask gwc (MMA+softmax, 768thr) + mask cat
    cudaFuncSetAttribute(stage2, cudaFuncAttributeMaxDynamicSharedMemorySize, SMEM_S2);
    stage2<<<360 + 60, 768, SMEM_S2>>>(y1g, w2hi, w2lo, mg, y1c, c_w2, mc);

    // 3) aggregation
    stage3<<<2880 + 2160, 256>>>(gwc_f, mg, g8, cat_f, mc, c8);

    // 4) cost volumes
    stage4<<<2*8*HO + 2*24*HO, 144>>>(g8, c8, out);
}